// round 2
// baseline (speedup 1.0000x reference)
#include <cuda_runtime.h>

#define T_TOK 20000
#define LDP   152
typedef unsigned long long ull;

// ---- scratch (device globals) ----
__device__ __align__(256) float g_AH1[T_TOK * LDP];
__device__ __align__(256) float g_AH2[T_TOK * LDP];
__device__ __align__(256) float g_AP [T_TOK * LDP];
__device__ __align__(256) float g_BP [T_TOK * LDP];
__device__ __align__(256) float g_PP [T_TOK * LDP];
__device__ __align__(256) float g_LG [T_TOK];

// ---- packed f32x2 helpers ----
__device__ __forceinline__ ull ffma2(ull a, ull b, ull c) {
    ull d; asm("fma.rn.f32x2 %0, %1, %2, %3;" : "=l"(d) : "l"(a), "l"(b), "l"(c));
    return d;
}
__device__ __forceinline__ float2 upk2(ull v) {
    float2 r; asm("mov.b64 {%0,%1}, %2;" : "=f"(r.x), "=f"(r.y) : "l"(v));
    return r;
}
__device__ __forceinline__ ull pk2(float lo, float hi) {
    ull r; asm("mov.b64 %0, {%1,%2};" : "=l"(r) : "f"(lo), "f"(hi));
    return r;
}

#define FMA16(A, x0, x1, x2, x3, wA, wB)                                   \
    A[0][0] = ffma2(x0, wA.x, A[0][0]); A[0][1] = ffma2(x0, wA.y, A[0][1]); \
    A[0][2] = ffma2(x0, wB.x, A[0][2]); A[0][3] = ffma2(x0, wB.y, A[0][3]); \
    A[1][0] = ffma2(x1, wA.x, A[1][0]); A[1][1] = ffma2(x1, wA.y, A[1][1]); \
    A[1][2] = ffma2(x1, wB.x, A[1][2]); A[1][3] = ffma2(x1, wB.y, A[1][3]); \
    A[2][0] = ffma2(x2, wA.x, A[2][0]); A[2][1] = ffma2(x2, wA.y, A[2][1]); \
    A[2][2] = ffma2(x2, wB.x, A[2][2]); A[2][3] = ffma2(x2, wB.y, A[2][3]); \
    A[3][0] = ffma2(x3, wA.x, A[3][0]); A[3][1] = ffma2(x3, wA.y, A[3][1]); \
    A[3][2] = ffma2(x3, wB.x, A[3][2]); A[3][3] = ffma2(x3, wB.y, A[3][3]);

// ============================================================
// GEMM: Y[M,150] = opt_relu(X[M,K] @ W[K,150] + bias), Y stride LDP.
// 64 rows x 160 cols per block, 320 threads, f32x2 row-paired accums.
// Xs: transposed [32][66]; Wd: duplicated pairs [32][320].
// ============================================================
#define GEMM_SMEM_FLOATS (2112 + 10240)

__global__ __launch_bounds__(320, 2) void gemm150(
    const float* __restrict__ X, int ldx, int K,
    const float* __restrict__ W,
    const float* __restrict__ bias,
    float* __restrict__ Y, int M, int dorelu)
{
    extern __shared__ float sm[];
    float* Xs = sm;          // [kk][i]  stride 66
    float* Wd = sm + 2112;   // [kk][2c] stride 320

    const int tid = threadIdx.x;
    const int sg  = tid / 40;
    const int cg  = tid % 40;
    const int c0  = cg * 4;
    const int m0  = blockIdx.x * 64;

    ull acc[4][4];
#pragma unroll
    for (int p = 0; p < 4; p++)
#pragma unroll
        for (int c = 0; c < 4; c++) acc[p][c] = 0ull;

    const int ktiles = (K + 31) >> 5;
    for (int kt = 0; kt < ktiles; kt++) {
        const int kb = kt << 5;
        for (int idx = tid; idx < 2048; idx += 320) {
            int i = idx >> 5, kk = idx & 31;
            int m = m0 + i, k = kb + kk;
            Xs[kk * 66 + i] = (m < M && k < K) ? X[(size_t)m * ldx + k] : 0.f;
        }
        for (int idx = tid; idx < 5120; idx += 320) {
            int kk = idx / 160, c = idx - kk * 160;
            int k = kb + kk;
            float v = (k < K && c < 150) ? W[k * 150 + c] : 0.f;
            Wd[kk * 320 + 2 * c]     = v;
            Wd[kk * 320 + 2 * c + 1] = v;
        }
        __syncthreads();
#pragma unroll 8
        for (int kk = 0; kk < 32; kk++) {
            const ull* xr = (const ull*)(Xs + kk * 66 + sg * 8);
            ull x0 = xr[0], x1 = xr[1], x2 = xr[2], x3 = xr[3];
            const ulonglong2* wp = (const ulonglong2*)(Wd + kk * 320 + 2 * c0);
            ulonglong2 wA = wp[0], wB = wp[1];
            FMA16(acc, x0, x1, x2, x3, wA, wB);
        }
        __syncthreads();
    }

    if (c0 >= 152) return;  // cg 38,39 hold only pad columns
    float bb0 = 0.f, bb1 = 0.f, bb2 = 0.f, bb3 = 0.f;
    if (bias) {
        bb0 = (c0     < 150) ? bias[c0]     : 0.f;
        bb1 = (c0 + 1 < 150) ? bias[c0 + 1] : 0.f;
        bb2 = (c0 + 2 < 150) ? bias[c0 + 2] : 0.f;
        bb3 = (c0 + 3 < 150) ? bias[c0 + 3] : 0.f;
    }
#pragma unroll
    for (int p = 0; p < 4; p++) {
        int mA = m0 + sg * 8 + 2 * p;
        float2 q0 = upk2(acc[p][0]), q1 = upk2(acc[p][1]);
        float2 q2 = upk2(acc[p][2]), q3 = upk2(acc[p][3]);
        float4 vA = make_float4(q0.x + bb0, q1.x + bb1, q2.x + bb2, q3.x + bb3);
        float4 vB = make_float4(q0.y + bb0, q1.y + bb1, q2.y + bb2, q3.y + bb3);
        if (dorelu) {
            vA.x = fmaxf(vA.x, 0.f); vA.y = fmaxf(vA.y, 0.f);
            vA.z = fmaxf(vA.z, 0.f); vA.w = fmaxf(vA.w, 0.f);
            vB.x = fmaxf(vB.x, 0.f); vB.y = fmaxf(vB.y, 0.f);
            vB.z = fmaxf(vB.z, 0.f); vB.w = fmaxf(vB.w, 0.f);
        }
        if (mA < M)     *(float4*)(Y + (size_t)mA * LDP + c0)       = vA;
        if (mA + 1 < M) *(float4*)(Y + (size_t)(mA + 1) * LDP + c0) = vB;
    }
}

// ============================================================
// logits[r] = AH2[r,:150] . W3 + b3   (warp per row)
// ============================================================
__global__ void logits_k(const float* __restrict__ AH2,
                         const float* __restrict__ W3,
                         const float* __restrict__ b3,
                         float* __restrict__ logits, int M)
{
    int warp = (blockIdx.x * blockDim.x + threadIdx.x) >> 5;
    int lane = threadIdx.x & 31;
    if (warp >= M) return;
    float sum = 0.f;
    for (int c = lane; c < 150; c += 32)
        sum += AH2[(size_t)warp * LDP + c] * W3[c];
#pragma unroll
    for (int o = 16; o; o >>= 1) sum += __shfl_xor_sync(0xffffffffu, sum, o);
    if (lane == 0) logits[warp] = sum + b3[0];
}

// ============================================================
// Span kernel (f32x2 stage B).
// smem floats: W2d[25*320]@0, H1T[150*66]@8000, wgt[640]@17900,
//              red[64*41]@18540, b1s[160]@21164, b2s[160]@21324,
//              W3s[160]@21484  -> total 21644 floats = 86576 B
// ============================================================
#define SPAN_SMEM_FLOATS 21644

__global__ __launch_bounds__(320, 2) void span_k(
    const float* __restrict__ AP, const float* __restrict__ BP,
    const float* __restrict__ PP, const float* __restrict__ logits,
    const float* __restrict__ W2, const float* __restrict__ b1,
    const float* __restrict__ b2, const float* __restrict__ W3,
    const float* __restrict__ b3, float* __restrict__ out)
{
    extern __shared__ float sm[];
    float* W2d = sm;            // [kk][2c] stride 320, 25 rows
    float* H1T = sm + 8000;     // [k][i]   stride 66, 150 rows
    float* wgt = sm + 17900;
    float* red = sm + 18540;
    float* b1s = sm + 21164;
    float* b2s = sm + 21324;
    float* W3s = sm + 21484;

    const int n  = blockIdx.y + 1;
    const int S  = T_TOK - n + 1;
    const int s0 = blockIdx.x * 64;
    if (s0 >= S) return;

    const int tid = threadIdx.x;
    const int sg  = tid / 40;
    const int cg  = tid % 40;
    const int c0  = cg * 4;

    for (int c = tid; c < 160; c += 320) {
        b1s[c] = (c < 150) ? b1[c] : 0.f;
        b2s[c] = (c < 150) ? b2[c] : 0.f;
        W3s[c] = (c < 150) ? W3[c] : 0.f;
    }

    if (tid < 64) {
        int s = s0 + tid;
        if (s < S) {
            float mx = -1e30f;
            for (int j = 0; j < n; j++) mx = fmaxf(mx, logits[s + j]);
            float sum = 0.f;
            for (int j = 0; j < n; j++) {
                float e = __expf(logits[s + j] - mx);
                wgt[tid * 10 + j] = e;
                sum += e;
            }
            float inv = 1.f / sum;
            for (int j = 0; j < n; j++) wgt[tid * 10 + j] *= inv;
            for (int j = n; j < 10; j++) wgt[tid * 10 + j] = 0.f;
        } else {
            for (int j = 0; j < 10; j++) wgt[tid * 10 + j] = 0.f;
        }
    }
    __syncthreads();

    // ---- Stage A: H1 tile, stored TRANSPOSED H1T[k][span] ----
    if (c0 < 152) {
#pragma unroll
        for (int r = 0; r < 8; r++) {
            int i = sg * 8 + r;
            int s = s0 + i;
            float4 v = make_float4(0.f, 0.f, 0.f, 0.f);
            if (s < S) {
                int e = s + n - 1;
                float4 a4 = *(const float4*)(AP + (size_t)s * LDP + c0);
                float4 q4 = *(const float4*)(BP + (size_t)e * LDP + c0);
                float4 o4 = *(const float4*)(b1s + c0);
                v.x = a4.x + q4.x + o4.x;
                v.y = a4.y + q4.y + o4.y;
                v.z = a4.z + q4.z + o4.z;
                v.w = a4.w + q4.w + o4.w;
                for (int j = 0; j < n; j++) {
                    float w = wgt[i * 10 + j];
                    float4 p4 = *(const float4*)(PP + (size_t)(s + j) * LDP + c0);
                    v.x += w * p4.x; v.y += w * p4.y;
                    v.z += w * p4.z; v.w += w * p4.w;
                }
                v.x = fmaxf(v.x, 0.f); v.y = fmaxf(v.y, 0.f);
                v.z = fmaxf(v.z, 0.f); v.w = fmaxf(v.w, 0.f);
            }
            if (c0     < 150) H1T[(c0    ) * 66 + i] = v.x;
            if (c0 + 1 < 150) H1T[(c0 + 1) * 66 + i] = v.y;
            if (c0 + 2 < 150) H1T[(c0 + 2) * 66 + i] = v.z;
            if (c0 + 3 < 150) H1T[(c0 + 3) * 66 + i] = v.w;
        }
    }
    __syncthreads();

    // ---- Stage B: H2 = relu(H1 @ W2 + b2), 6 k-tiles of 25, f32x2 ----
    ull acc[4][4];
#pragma unroll
    for (int p = 0; p < 4; p++)
#pragma unroll
        for (int c = 0; c < 4; c++) {
            float bb = b2s[c0 + c];
            acc[p][c] = pk2(bb, bb);
        }

    for (int kt = 0; kt < 6; kt++) {
        const int kb = kt * 25;
        for (int idx = tid; idx < 4000; idx += 320) {
            int kk = idx / 160, c = idx - kk * 160;
            float v = (c < 150) ? W2[(kb + kk) * 150 + c] : 0.f;
            W2d[kk * 320 + 2 * c]     = v;
            W2d[kk * 320 + 2 * c + 1] = v;
        }
        __syncthreads();
#pragma unroll 5
        for (int kk = 0; kk < 25; kk++) {
            const ull* xr = (const ull*)(H1T + (kb + kk) * 66 + sg * 8);
            ull x0 = xr[0], x1 = xr[1], x2 = xr[2], x3 = xr[3];
            const ulonglong2* wp = (const ulonglong2*)(W2d + kk * 320 + 2 * c0);
            ulonglong2 wA = wp[0], wB = wp[1];
            FMA16(acc, x0, x1, x2, x3, wA, wB);
        }
        __syncthreads();
    }

    // ---- relu + W3 dot + block reduction ----
    float w30 = W3s[c0], w31 = W3s[c0 + 1], w32 = W3s[c0 + 2], w33 = W3s[c0 + 3];
#pragma unroll
    for (int p = 0; p < 4; p++) {
        float2 q0 = upk2(acc[p][0]), q1 = upk2(acc[p][1]);
        float2 q2 = upk2(acc[p][2]), q3 = upk2(acc[p][3]);
        float sLo = fmaxf(q0.x, 0.f) * w30 + fmaxf(q1.x, 0.f) * w31
                  + fmaxf(q2.x, 0.f) * w32 + fmaxf(q3.x, 0.f) * w33;
        float sHi = fmaxf(q0.y, 0.f) * w30 + fmaxf(q1.y, 0.f) * w31
                  + fmaxf(q2.y, 0.f) * w32 + fmaxf(q3.y, 0.f) * w33;
        red[(sg * 8 + 2 * p)     * 41 + cg] = sLo;
        red[(sg * 8 + 2 * p + 1) * 41 + cg] = sHi;
    }
    __syncthreads();

    if (tid < 64) {
        int s = s0 + tid;
        if (s < S) {
            float sum = 0.f;
            for (int j = 0; j < 40; j++) sum += red[tid * 41 + j];
            long long off = (long long)(n - 1) * (T_TOK + 1)
                          - (long long)(n - 1) * n / 2;
            out[off + s] = sum + b3[0];
        }
    }
}

// ============================================================
extern "C" void kernel_launch(void* const* d_in, const int* in_sizes, int n_in,
                              void* d_out, int out_size)
{
    const float* embeds  = (const float*)d_in[0];
    const float* states  = (const float*)d_in[1];
    const float* attn_W1 = (const float*)d_in[2];
    const float* attn_b1 = (const float*)d_in[3];
    const float* attn_W2 = (const float*)d_in[4];
    const float* attn_b2 = (const float*)d_in[5];
    const float* attn_W3 = (const float*)d_in[6];
    const float* attn_b3 = (const float*)d_in[7];
    const float* sc_W1   = (const float*)d_in[8];
    const float* sc_b1   = (const float*)d_in[9];
    const float* sc_W2   = (const float*)d_in[10];
    const float* sc_b2   = (const float*)d_in[11];
    const float* sc_W3   = (const float*)d_in[12];
    const float* sc_b3   = (const float*)d_in[13];
    float* out = (float*)d_out;

    float *AH1, *AH2, *AP, *BP, *PP, *LG;
    cudaGetSymbolAddress((void**)&AH1, g_AH1);
    cudaGetSymbolAddress((void**)&AH2, g_AH2);
    cudaGetSymbolAddress((void**)&AP,  g_AP);
    cudaGetSymbolAddress((void**)&BP,  g_BP);
    cudaGetSymbolAddress((void**)&PP,  g_PP);
    cudaGetSymbolAddress((void**)&LG,  g_LG);

    const int gm = (T_TOK + 63) / 64;  // 313

    size_t gsm = GEMM_SMEM_FLOATS * sizeof(float);  // 49408 B
    cudaFuncSetAttribute(gemm150, cudaFuncAttributeMaxDynamicSharedMemorySize, (int)gsm);

    // attention MLP
    gemm150<<<gm, 320, gsm>>>(states, 400, 400, attn_W1, attn_b1, AH1, T_TOK, 1);
    gemm150<<<gm, 320, gsm>>>(AH1,   LDP, 150, attn_W2, attn_b2, AH2, T_TOK, 1);
    logits_k<<<(T_TOK * 32 + 255) / 256, 256>>>(AH2, attn_W3, attn_b3, LG, T_TOK);

    // span layer-1 projections (bias deferred to span kernel)
    gemm150<<<gm, 320, gsm>>>(states, 400, 400, sc_W1,             nullptr, AP, T_TOK, 0);
    gemm150<<<gm, 320, gsm>>>(states, 400, 400, sc_W1 + 400 * 150, nullptr, BP, T_TOK, 0);
    gemm150<<<gm, 320, gsm>>>(embeds, 300, 300, sc_W1 + 800 * 150, nullptr, PP, T_TOK, 0);

    // fused span scorer
    size_t ssm = SPAN_SMEM_FLOATS * sizeof(float);  // 86576 B
    cudaFuncSetAttribute(span_k, cudaFuncAttributeMaxDynamicSharedMemorySize, (int)ssm);
    span_k<<<dim3(gm, 10), 320, ssm>>>(AP, BP, PP, LG,
                                       sc_W2, sc_b1, sc_b2, sc_W3, sc_b3, out);
}

// round 3
// speedup vs baseline: 2.0742x; 2.0742x over previous
#include <cuda_runtime.h>
#include <cuda_bf16.h>

#define T_TOK 20000
#define LDO   160   // padded col count for all [T,150] intermediates

// ---------------- scratch ----------------
__device__ __align__(256) float g_AH1[T_TOK * LDO];
__device__ __align__(256) float g_AH2[T_TOK * LDO];
__device__ __align__(256) float g_AP [T_TOK * LDO];
__device__ __align__(256) float g_BP [T_TOK * LDO];
__device__ __align__(256) float g_PP [T_TOK * LDO];
__device__ __align__(256) float g_LG [T_TOK];

// weight images: per chunk: 160 rows(n) x 40 bf16 (16 hi | 16 lo | 8 pad)
// chunks: attn1:25, scA:25, scB:25, scP:19, attn2:10, W2:10  -> 114 chunks
#define CH_ELEMS 6400
#define O_A1 0
#define O_SA (25 * CH_ELEMS)
#define O_SB (50 * CH_ELEMS)
#define O_SP (75 * CH_ELEMS)
#define O_A2 (94 * CH_ELEMS)
#define O_W2 (104 * CH_ELEMS)
__device__ __align__(256) __nv_bfloat16 g_Wimg[114 * CH_ELEMS];

// padded bias / W3 arrays [160]
__device__ __align__(256) float g_ba1[160];
__device__ __align__(256) float g_ba2[160];
__device__ __align__(256) float g_b1 [160];
__device__ __align__(256) float g_b2 [160];
__device__ __align__(256) float g_w3 [160];

// ---------------- mma / ldmatrix helpers ----------------
__device__ __forceinline__ unsigned cvta_s(const void* p) {
    return (unsigned)__cvta_generic_to_shared(p);
}
__device__ __forceinline__ void ldmx4(unsigned* r, unsigned addr) {
    asm volatile("ldmatrix.sync.aligned.m8n8.x4.shared.b16 {%0,%1,%2,%3}, [%4];"
        : "=r"(r[0]), "=r"(r[1]), "=r"(r[2]), "=r"(r[3]) : "r"(addr));
}
__device__ __forceinline__ void mma16816(float* d, const unsigned* a, const unsigned* b) {
    asm volatile(
        "mma.sync.aligned.m16n8k16.row.col.f32.bf16.bf16.f32 "
        "{%0,%1,%2,%3}, {%4,%5,%6,%7}, {%8,%9}, {%0,%1,%2,%3};"
        : "+f"(d[0]), "+f"(d[1]), "+f"(d[2]), "+f"(d[3])
        : "r"(a[0]), "r"(a[1]), "r"(a[2]), "r"(a[3]), "r"(b[0]), "r"(b[1]));
}
__device__ __forceinline__ void split_bf16(float v, unsigned short& h, unsigned short& l) {
    __nv_bfloat16 hb = __float2bfloat16_rn(v);
    __nv_bfloat16 lb = __float2bfloat16_rn(v - __bfloat162float(hb));
    h = __bfloat16_as_ushort(hb);
    l = __bfloat16_as_ushort(lb);
}

// ---------------- prep kernels ----------------
__global__ void prep_w(const float* __restrict__ W, int K, int chunks,
                       __nv_bfloat16* __restrict__ img)
{
    int total = chunks * 2560;
    for (int idx = blockIdx.x * blockDim.x + threadIdx.x; idx < total;
         idx += gridDim.x * blockDim.x) {
        int c   = idx / 2560;
        int rem = idx - c * 2560;
        int n   = rem >> 4;
        int kk  = rem & 15;
        int k   = c * 16 + kk;
        float v = (k < K && n < 150) ? W[k * 150 + n] : 0.f;
        unsigned short h, l;
        split_bf16(v, h, l);
        unsigned short* dst = (unsigned short*)(img + (size_t)(c * 160 + n) * 40);
        dst[kk]      = h;
        dst[16 + kk] = l;
        if (kk < 8) dst[32 + kk] = 0;
    }
}

__global__ void prep_bias(const float* a1, const float* a2, const float* b1,
                          const float* b2, const float* w3)
{
    int j = threadIdx.x;  // 160
    bool ok = j < 150;
    g_ba1[j] = ok ? a1[j] : 0.f;
    g_ba2[j] = ok ? a2[j] : 0.f;
    g_b1[j]  = ok ? b1[j] : 0.f;
    g_b2[j]  = ok ? b2[j] : 0.f;
    g_w3[j]  = ok ? w3[j] : 0.f;
}

// ---------------- staging helpers ----------------
// A chunk: 64 rows x 16 k -> smem [r][40bf16] (hi@0, lo@16). 256 threads.
__device__ __forceinline__ void stage_A(const float* __restrict__ X, int ldx,
                                        int Kreal, int m0, int M, int c,
                                        __nv_bfloat16* __restrict__ Abuf, int tid)
{
    int r  = tid >> 2;
    int kq = tid & 3;
    int m  = m0 + r;
    int k0 = c * 16 + kq * 4;
    float4 v = make_float4(0.f, 0.f, 0.f, 0.f);
    if (m < M) {
        if (k0 + 3 < Kreal) {
            v = *(const float4*)(X + (size_t)m * ldx + k0);
        } else {
            float* pv = (float*)&v;
            for (int j = 0; j < 4; j++)
                if (k0 + j < Kreal) pv[j] = X[(size_t)m * ldx + k0 + j];
        }
    }
    unsigned short h[4], l[4];
    split_bf16(v.x, h[0], l[0]); split_bf16(v.y, h[1], l[1]);
    split_bf16(v.z, h[2], l[2]); split_bf16(v.w, h[3], l[3]);
    unsigned short* dst = (unsigned short*)(Abuf + r * 40 + kq * 4);
    *(uint2*)dst        = make_uint2((unsigned)h[0] | ((unsigned)h[1] << 16),
                                     (unsigned)h[2] | ((unsigned)h[3] << 16));
    *(uint2*)(dst + 16) = make_uint2((unsigned)l[0] | ((unsigned)l[1] << 16),
                                     (unsigned)l[2] | ((unsigned)l[3] << 16));
}

// B chunk copy: 160x40 bf16 = 800 float4
__device__ __forceinline__ void stage_B(const __nv_bfloat16* __restrict__ img, int c,
                                        __nv_bfloat16* __restrict__ Bbuf, int tid)
{
    const float4* src = (const float4*)(img + (size_t)c * CH_ELEMS);
    float4* dst = (float4*)Bbuf;
    for (int i = tid; i < 800; i += 256) dst[i] = src[i];
}

// ---------------- GEMM: Y[M,160] = act(X[M,K] @ W + bias) ----------------
__global__ __launch_bounds__(256, 2) void mma_gemm(
    const float* __restrict__ X, int ldx, int Kreal, int chunks,
    const __nv_bfloat16* __restrict__ Wimg,
    const float* __restrict__ biasPad, int dorelu,
    float* __restrict__ Y, int M)
{
    __shared__ __nv_bfloat16 As[2 * 64 * 40];
    __shared__ __nv_bfloat16 Bs[2 * 160 * 40];

    const int tid  = threadIdx.x;
    const int lane = tid & 31;
    const int warp = tid >> 5;
    const int mw   = warp & 3;
    const int nw   = warp >> 2;
    const int m0   = blockIdx.x * 64;

    float acc[10][4];
#pragma unroll
    for (int t = 0; t < 10; t++)
#pragma unroll
        for (int j = 0; j < 4; j++) acc[t][j] = 0.f;

    const int aRow = (lane & 7) + ((lane & 8) ? 8 : 0);
    const unsigned aOff = (unsigned)((mw * 16 + aRow) * 80 + ((lane & 16) ? 16 : 0));
    const int bRow = (lane & 7) + ((lane & 16) ? 8 : 0);
    const unsigned bOff = (unsigned)(bRow * 80 + ((lane & 8) ? 16 : 0));

    const unsigned asBase = cvta_s(As);
    const unsigned bsBase = cvta_s(Bs);

    stage_A(X, ldx, Kreal, m0, M, 0, As, tid);
    stage_B(Wimg, 0, Bs, tid);
    __syncthreads();

    for (int c = 0; c < chunks; c++) {
        int cur = c & 1;
        if (c + 1 < chunks) {
            stage_A(X, ldx, Kreal, m0, M, c + 1, As + (cur ^ 1) * 2560, tid);
            stage_B(Wimg, c + 1, Bs + (cur ^ 1) * 6400, tid);
        }
        unsigned aBuf = asBase + cur * 5120;
        unsigned bBuf = bsBase + cur * 12800;
        unsigned ah[4], al[4];
        ldmx4(ah, aBuf + aOff);
        ldmx4(al, aBuf + aOff + 32);
#pragma unroll
        for (int p = 0; p < 5; p++) {
            unsigned bh[4], bl[4];
            unsigned baddr = bBuf + (unsigned)((nw * 80 + p * 16) * 80) + bOff;
            ldmx4(bh, baddr);
            ldmx4(bl, baddr + 32);
            mma16816(acc[2 * p],     ah, bh);
            mma16816(acc[2 * p],     ah, bl);
            mma16816(acc[2 * p],     al, bh);
            mma16816(acc[2 * p + 1], ah, bh + 2);
            mma16816(acc[2 * p + 1], ah, bl + 2);
            mma16816(acc[2 * p + 1], al, bh + 2);
        }
        __syncthreads();
    }

    const int r1 = m0 + mw * 16 + (lane >> 2);
    const int cBase = nw * 80 + 2 * (lane & 3);
#pragma unroll
    for (int t = 0; t < 10; t++) {
        int col = cBase + t * 8;
        float b0 = 0.f, b1v = 0.f;
        if (biasPad) { b0 = biasPad[col]; b1v = biasPad[col + 1]; }
        float2 vA = make_float2(acc[t][0] + b0, acc[t][1] + b1v);
        float2 vB = make_float2(acc[t][2] + b0, acc[t][3] + b1v);
        if (dorelu) {
            vA.x = fmaxf(vA.x, 0.f); vA.y = fmaxf(vA.y, 0.f);
            vB.x = fmaxf(vB.x, 0.f); vB.y = fmaxf(vB.y, 0.f);
        }
        if (r1 < M)     *(float2*)(Y + (size_t)r1 * LDO + col)       = vA;
        if (r1 + 8 < M) *(float2*)(Y + (size_t)(r1 + 8) * LDO + col) = vB;
    }
}

// ---------------- logits ----------------
__global__ void logits_k(const float* __restrict__ AH2,
                         const float* __restrict__ W3,
                         const float* __restrict__ b3,
                         float* __restrict__ logits, int M)
{
    int warp = (blockIdx.x * blockDim.x + threadIdx.x) >> 5;
    int lane = threadIdx.x & 31;
    if (warp >= M) return;
    float sum = 0.f;
    for (int c = lane; c < 150; c += 32)
        sum += AH2[(size_t)warp * LDO + c] * W3[c];
#pragma unroll
    for (int o = 16; o; o >>= 1) sum += __shfl_xor_sync(0xffffffffu, sum, o);
    if (lane == 0) logits[warp] = sum + b3[0];
}

// ---------------- span kernel ----------------
// smem bytes: W2s 2*12800 @0, H1s 10*64*80 @25600, wgt 64*10*4 @76800,
//             red 64*2*4 @79360  -> total 79872
#define SPAN_SMEM 79872

__global__ __launch_bounds__(256, 2) void span_k(
    const float* __restrict__ AP, const float* __restrict__ BP,
    const float* __restrict__ PP, const float* __restrict__ logits,
    const __nv_bfloat16* __restrict__ W2img,
    const float* __restrict__ b3, float* __restrict__ out)
{
    extern __shared__ char sm[];
    __nv_bfloat16* W2s = (__nv_bfloat16*)sm;
    __nv_bfloat16* H1s = (__nv_bfloat16*)(sm + 25600);
    float* wgt = (float*)(sm + 76800);
    float* red = (float*)(sm + 79360);

    const int n  = blockIdx.y + 1;
    const int S  = T_TOK - n + 1;
    const int s0 = blockIdx.x * 64;

    const int tid  = threadIdx.x;
    const int lane = tid & 31;
    const int warp = tid >> 5;
    const int mw   = warp & 3;
    const int nw   = warp >> 2;

    // softmax weights
    if (tid < 64) {
        int s = s0 + tid;
        if (s < S) {
            float mx = -1e30f;
            for (int j = 0; j < n; j++) mx = fmaxf(mx, logits[s + j]);
            float sum = 0.f;
            for (int j = 0; j < n; j++) {
                float e = __expf(logits[s + j] - mx);
                wgt[tid * 10 + j] = e;
                sum += e;
            }
            float inv = 1.f / sum;
            for (int j = 0; j < n; j++) wgt[tid * 10 + j] *= inv;
        }
    }
    __syncthreads();

    // stage A: H1 = relu(AP[s] + BP[e] + b1 + sum_j w_j PP[s+j]) -> split hi/lo
#pragma unroll
    for (int it = 0; it < 10; it++) {
        int idx = tid + it * 256;
        int i = idx / 40;
        int g = idx - i * 40;
        int s = s0 + i;
        float4 v = make_float4(0.f, 0.f, 0.f, 0.f);
        if (s < S) {
            int c0 = g * 4;
            float4 a4 = *(const float4*)(AP + (size_t)s * LDO + c0);
            float4 q4 = *(const float4*)(BP + (size_t)(s + n - 1) * LDO + c0);
            float4 b4 = *(const float4*)(g_b1 + c0);
            v.x = a4.x + q4.x + b4.x;
            v.y = a4.y + q4.y + b4.y;
            v.z = a4.z + q4.z + b4.z;
            v.w = a4.w + q4.w + b4.w;
            for (int j = 0; j < n; j++) {
                float w = wgt[i * 10 + j];
                float4 p4 = *(const float4*)(PP + (size_t)(s + j) * LDO + c0);
                v.x += w * p4.x; v.y += w * p4.y;
                v.z += w * p4.z; v.w += w * p4.w;
            }
            v.x = fmaxf(v.x, 0.f); v.y = fmaxf(v.y, 0.f);
            v.z = fmaxf(v.z, 0.f); v.w = fmaxf(v.w, 0.f);
        }
        unsigned short h[4], l[4];
        split_bf16(v.x, h[0], l[0]); split_bf16(v.y, h[1], l[1]);
        split_bf16(v.z, h[2], l[2]); split_bf16(v.w, h[3], l[3]);
        int cch = g >> 2, kk = (g & 3) * 4;
        unsigned short* dst = (unsigned short*)(H1s + (size_t)(cch * 64 + i) * 40 + kk);
        *(uint2*)dst        = make_uint2((unsigned)h[0] | ((unsigned)h[1] << 16),
                                         (unsigned)h[2] | ((unsigned)h[3] << 16));
        *(uint2*)(dst + 16) = make_uint2((unsigned)l[0] | ((unsigned)l[1] << 16),
                                         (unsigned)l[2] | ((unsigned)l[3] << 16));
    }
    stage_B(W2img, 0, W2s, tid);
    __syncthreads();

    // stage B: H2 = relu(H1 @ W2 + b2) via mma, 10 k-chunks
    float acc[10][4];
#pragma unroll
    for (int t = 0; t < 10; t++)
#pragma unroll
        for (int j = 0; j < 4; j++) acc[t][j] = 0.f;

    const int aRow = (lane & 7) + ((lane & 8) ? 8 : 0);
    const unsigned aOff = (unsigned)((mw * 16 + aRow) * 80 + ((lane & 16) ? 16 : 0));
    const int bRow = (lane & 7) + ((lane & 16) ? 8 : 0);
    const unsigned bOff = (unsigned)(bRow * 80 + ((lane & 8) ? 16 : 0));
    const unsigned h1Base = cvta_s(H1s);
    const unsigned w2Base = cvta_s(W2s);

    for (int c = 0; c < 10; c++) {
        int cur = c & 1;
        if (c + 1 < 10) stage_B(W2img, c + 1, W2s + (cur ^ 1) * 6400, tid);
        unsigned aBuf = h1Base + (unsigned)(c * 64 * 80);
        unsigned bBuf = w2Base + cur * 12800;
        unsigned ah[4], al[4];
        ldmx4(ah, aBuf + aOff);
        ldmx4(al, aBuf + aOff + 32);
#pragma unroll
        for (int p = 0; p < 5; p++) {
            unsigned bh[4], bl[4];
            unsigned baddr = bBuf + (unsigned)((nw * 80 + p * 16) * 80) + bOff;
            ldmx4(bh, baddr);
            ldmx4(bl, baddr + 32);
            mma16816(acc[2 * p],     ah, bh);
            mma16816(acc[2 * p],     ah, bl);
            mma16816(acc[2 * p],     al, bh);
            mma16816(acc[2 * p + 1], ah, bh + 2);
            mma16816(acc[2 * p + 1], ah, bl + 2);
            mma16816(acc[2 * p + 1], al, bh + 2);
        }
        __syncthreads();
    }

    // epilogue: relu(H2) . W3, reduce
    const int cBase = nw * 80 + 2 * (lane & 3);
    float s1 = 0.f, s2 = 0.f;
#pragma unroll
    for (int t = 0; t < 10; t++) {
        int col = cBase + t * 8;
        float2 w3 = *(const float2*)(g_w3 + col);
        float2 b2 = *(const float2*)(g_b2 + col);
        s1 += fmaxf(acc[t][0] + b2.x, 0.f) * w3.x + fmaxf(acc[t][1] + b2.y, 0.f) * w3.y;
        s2 += fmaxf(acc[t][2] + b2.x, 0.f) * w3.x + fmaxf(acc[t][3] + b2.y, 0.f) * w3.y;
    }
    s1 += __shfl_xor_sync(0xffffffffu, s1, 1);
    s1 += __shfl_xor_sync(0xffffffffu, s1, 2);
    s2 += __shfl_xor_sync(0xffffffffu, s2, 1);
    s2 += __shfl_xor_sync(0xffffffffu, s2, 2);
    if ((lane & 3) == 0) {
        int row = mw * 16 + (lane >> 2);
        red[row * 2 + nw]       = s1;
        red[(row + 8) * 2 + nw] = s2;
    }
    __syncthreads();

    if (tid < 64) {
        int s = s0 + tid;
        if (s < S) {
            long long off = (long long)(n - 1) * (T_TOK + 1)
                          - (long long)(n - 1) * n / 2;
            out[off + s] = red[tid * 2] + red[tid * 2 + 1] + b3[0];
        }
    }
}

// ---------------- host ----------------
extern "C" void kernel_launch(void* const* d_in, const int* in_sizes, int n_in,
                              void* d_out, int out_size)
{
    const float* embeds  = (const float*)d_in[0];
    const float* states  = (const float*)d_in[1];
    const float* attn_W1 = (const float*)d_in[2];
    const float* attn_b1 = (const float*)d_in[3];
    const float* attn_W2 = (const float*)d_in[4];
    const float* attn_b2 = (const float*)d_in[5];
    const float* attn_W3 = (const float*)d_in[6];
    const float* attn_b3 = (const float*)d_in[7];
    const float* sc_W1   = (const float*)d_in[8];
    const float* sc_b1   = (const float*)d_in[9];
    const float* sc_W2   = (const float*)d_in[10];
    const float* sc_b2   = (const float*)d_in[11];
    const float* sc_W3   = (const float*)d_in[12];
    const float* sc_b3   = (const float*)d_in[13];
    float* out = (float*)d_out;

    float *AH1, *AH2, *AP, *BP, *PP, *LG;
    __nv_bfloat16* Wimg;
    float *ba1, *ba2;
    cudaGetSymbolAddress((void**)&AH1,  g_AH1);
    cudaGetSymbolAddress((void**)&AH2,  g_AH2);
    cudaGetSymbolAddress((void**)&AP,   g_AP);
    cudaGetSymbolAddress((void**)&BP,   g_BP);
    cudaGetSymbolAddress((void**)&PP,   g_PP);
    cudaGetSymbolAddress((void**)&LG,   g_LG);
    cudaGetSymbolAddress((void**)&Wimg, g_Wimg);
    cudaGetSymbolAddress((void**)&ba1,  g_ba1);
    cudaGetSymbolAddress((void**)&ba2,  g_ba2);

    // weight prep
    prep_w<<<64, 256>>>(attn_W1,            400, 25, Wimg + O_A1);
    prep_w<<<64, 256>>>(sc_W1,              400, 25, Wimg + O_SA);
    prep_w<<<64, 256>>>(sc_W1 + 400 * 150,  400, 25, Wimg + O_SB);
    prep_w<<<64, 256>>>(sc_W1 + 800 * 150,  300, 19, Wimg + O_SP);
    prep_w<<<32, 256>>>(attn_W2,            150, 10, Wimg + O_A2);
    prep_w<<<32, 256>>>(sc_W2,              150, 10, Wimg + O_W2);
    prep_bias<<<1, 160>>>(attn_b1, attn_b2, sc_b1, sc_b2, sc_W3);

    const int gm = (T_TOK + 63) / 64;  // 313

    // attention MLP + projections
    mma_gemm<<<gm, 256>>>(states, 400, 400, 25, Wimg + O_A1, ba1, 1, AH1, T_TOK);
    mma_gemm<<<gm, 256>>>(AH1,    LDO, 160, 10, Wimg + O_A2, ba2, 1, AH2, T_TOK);
    logits_k<<<(T_TOK * 32 + 255) / 256, 256>>>(AH2, attn_W3, attn_b3, LG, T_TOK);
    mma_gemm<<<gm, 256>>>(states, 400, 400, 25, Wimg + O_SA, nullptr, 0, AP, T_TOK);
    mma_gemm<<<gm, 256>>>(states, 400, 400, 25, Wimg + O_SB, nullptr, 0, BP, T_TOK);
    mma_gemm<<<gm, 256>>>(embeds, 300, 300, 19, Wimg + O_SP, nullptr, 0, PP, T_TOK);

    // fused span scorer
    cudaFuncSetAttribute(span_k, cudaFuncAttributeMaxDynamicSharedMemorySize, SPAN_SMEM);
    span_k<<<dim3(gm, 10), 256, SPAN_SMEM>>>(AP, BP, PP, LG, Wimg + O_W2, sc_b3, out);
}

// round 5
// speedup vs baseline: 2.5146x; 1.2123x over previous
#include <cuda_runtime.h>
#include <cuda_bf16.h>

#define T_TOK 20000
#define LDO   160

// ---------------- scratch ----------------
__device__ __align__(256) float g_AH1[T_TOK * LDO];
__device__ __align__(256) float g_AP [T_TOK * LDO];
__device__ __align__(256) float g_BP [T_TOK * LDO];
__device__ __align__(256) float g_PP [T_TOK * LDO];
__device__ __align__(256) float g_LG [T_TOK];
__device__ int g_ctr;

// weight images: per k16-chunk: 160 rows(n) x 40 bf16 (16 hi | 16 lo | 8 pad)
// global chunk order: attn1:25, scA:25, scB:25, scP:19, attn2:10, W2:10 -> 114
#define CH_ELEMS 6400
#define O_A1 0
#define O_SA (25 * CH_ELEMS)
#define O_SB (50 * CH_ELEMS)
#define O_SP (75 * CH_ELEMS)
#define O_A2 (94 * CH_ELEMS)
#define O_W2 (104 * CH_ELEMS)
__device__ __align__(256) __nv_bfloat16 g_Wimg[114 * CH_ELEMS];

__device__ __align__(256) float g_ba1[160];
__device__ __align__(256) float g_ba2[160];
__device__ __align__(256) float g_b1 [160];
__device__ __align__(256) float g_b2 [160];
__device__ __align__(256) float g_w3 [160];
__device__ __align__(256) float g_wa3[160];

// ---------------- helpers ----------------
__device__ __forceinline__ unsigned cvta_s(const void* p) {
    return (unsigned)__cvta_generic_to_shared(p);
}
__device__ __forceinline__ void ldmx4(unsigned* r, unsigned addr) {
    asm volatile("ldmatrix.sync.aligned.m8n8.x4.shared.b16 {%0,%1,%2,%3}, [%4];"
        : "=r"(r[0]), "=r"(r[1]), "=r"(r[2]), "=r"(r[3]) : "r"(addr));
}
__device__ __forceinline__ void mma16816(float* d, const unsigned* a, const unsigned* b) {
    asm volatile(
        "mma.sync.aligned.m16n8k16.row.col.f32.bf16.bf16.f32 "
        "{%0,%1,%2,%3}, {%4,%5,%6,%7}, {%8,%9}, {%0,%1,%2,%3};"
        : "+f"(d[0]), "+f"(d[1]), "+f"(d[2]), "+f"(d[3])
        : "r"(a[0]), "r"(a[1]), "r"(a[2]), "r"(a[3]), "r"(b[0]), "r"(b[1]));
}
__device__ __forceinline__ void split_bf16(float v, unsigned short& h, unsigned short& l) {
    __nv_bfloat16 hb = __float2bfloat16_rn(v);
    __nv_bfloat16 lb = __float2bfloat16_rn(v - __bfloat162float(hb));
    h = __bfloat16_as_ushort(hb);
    l = __bfloat16_as_ushort(lb);
}

// ---------------- single fused prep ----------------
__global__ void prep_all(const float* __restrict__ aW1, const float* __restrict__ scW1,
                         const float* __restrict__ aW2, const float* __restrict__ scW2,
                         const float* __restrict__ ab1, const float* __restrict__ ab2,
                         const float* __restrict__ sb1, const float* __restrict__ sb2,
                         const float* __restrict__ sW3, const float* __restrict__ aW3)
{
    int tid = threadIdx.x;
    if (blockIdx.x == 0) {
        if (tid < 160) {
            bool ok = tid < 150;
            g_ba1[tid] = ok ? ab1[tid] : 0.f;
            g_ba2[tid] = ok ? ab2[tid] : 0.f;
            g_b1 [tid] = ok ? sb1[tid] : 0.f;
            g_b2 [tid] = ok ? sb2[tid] : 0.f;
            g_w3 [tid] = ok ? sW3[tid] : 0.f;
            g_wa3[tid] = ok ? aW3[tid] : 0.f;
        }
        if (tid == 0) g_ctr = 0;
    }
    const int total = 114 * 2560;
    for (int idx = blockIdx.x * blockDim.x + tid; idx < total;
         idx += gridDim.x * blockDim.x) {
        int c   = idx / 2560;
        int rem = idx - c * 2560;
        int nn  = rem >> 4;
        int kk  = rem & 15;
        const float* W; int K; int lc;
        if      (c < 25)  { W = aW1;             K = 400; lc = c;       }
        else if (c < 50)  { W = scW1;            K = 400; lc = c - 25;  }
        else if (c < 75)  { W = scW1 + 400*150;  K = 400; lc = c - 50;  }
        else if (c < 94)  { W = scW1 + 800*150;  K = 300; lc = c - 75;  }
        else if (c < 104) { W = aW2;             K = 150; lc = c - 94;  }
        else              { W = scW2;            K = 150; lc = c - 104; }
        int k = lc * 16 + kk;
        float v = (k < K && nn < 150) ? W[k * 150 + nn] : 0.f;
        unsigned short h, l;
        split_bf16(v, h, l);
        unsigned short* dst = (unsigned short*)(g_Wimg + (size_t)c * CH_ELEMS + nn * 40);
        dst[kk]      = h;
        dst[16 + kk] = l;
        if (kk < 8) dst[32 + kk] = 0;
    }
}

// ---------------- staging helpers ----------------
__device__ __forceinline__ void stage_A(const float* __restrict__ X, int ldx,
                                        int Kreal, int m0, int M, int c,
                                        __nv_bfloat16* __restrict__ Abuf, int tid)
{
    int r  = tid >> 2;
    int kq = tid & 3;
    int m  = m0 + r;
    int k0 = c * 16 + kq * 4;
    float4 v = make_float4(0.f, 0.f, 0.f, 0.f);
    if (m < M) {
        if (k0 + 3 < Kreal) {
            v = *(const float4*)(X + (size_t)m * ldx + k0);
        } else {
            float* pv = (float*)&v;
            for (int j = 0; j < 4; j++)
                if (k0 + j < Kreal) pv[j] = X[(size_t)m * ldx + k0 + j];
        }
    }
    unsigned short h[4], l[4];
    split_bf16(v.x, h[0], l[0]); split_bf16(v.y, h[1], l[1]);
    split_bf16(v.z, h[2], l[2]); split_bf16(v.w, h[3], l[3]);
    unsigned short* dst = (unsigned short*)(Abuf + r * 40 + kq * 4);
    *(uint2*)dst        = make_uint2((unsigned)h[0] | ((unsigned)h[1] << 16),
                                     (unsigned)h[2] | ((unsigned)h[3] << 16));
    *(uint2*)(dst + 16) = make_uint2((unsigned)l[0] | ((unsigned)l[1] << 16),
                                     (unsigned)l[2] | ((unsigned)l[3] << 16));
}

__device__ __forceinline__ void stage_B(const __nv_bfloat16* __restrict__ img, int c,
                                        __nv_bfloat16* __restrict__ Bbuf, int tid)
{
    const float4* src = (const float4*)(img + (size_t)c * CH_ELEMS);
    float4* dst = (float4*)Bbuf;
    for (int i = tid; i < 800; i += 256) dst[i] = src[i];
}

// ---------------- core MMA tile macro-body ----------------
#define MMA_CHUNK(aBuf, bBuf)                                                   \
    {                                                                           \
        unsigned ah[4], al[4];                                                  \
        ldmx4(ah, (aBuf) + aOff);                                               \
        ldmx4(al, (aBuf) + aOff + 32);                                          \
        _Pragma("unroll")                                                       \
        for (int p = 0; p < 5; p++) {                                           \
            unsigned bh[4], bl[4];                                              \
            unsigned baddr = (bBuf) + (unsigned)((nw * 80 + p * 16) * 80) + bOff; \
            ldmx4(bh, baddr);                                                   \
            ldmx4(bl, baddr + 32);                                              \
            mma16816(acc[2 * p],     ah, bh);                                   \
            mma16816(acc[2 * p],     ah, bl);                                   \
            mma16816(acc[2 * p],     al, bh);                                   \
            mma16816(acc[2 * p + 1], ah, bh + 2);                               \
            mma16816(acc[2 * p + 1], ah, bl + 2);                               \
            mma16816(acc[2 * p + 1], al, bh + 2);                               \
        }                                                                       \
    }

// ---------------- batched GEMM: 4 independent jobs via blockIdx.y ----------------
__global__ __launch_bounds__(256, 2) void gemmA(
    const float* __restrict__ states, const float* __restrict__ embeds,
    float* __restrict__ AH1, float* __restrict__ AP,
    float* __restrict__ BP,  float* __restrict__ PP)
{
    __shared__ __nv_bfloat16 As[2 * 64 * 40];
    __shared__ __nv_bfloat16 Bs[2 * 160 * 40];

    const float* X; int ldx, Kreal, chunks; const __nv_bfloat16* img;
    const float* biasPad; int dorelu; float* Y;
    switch (blockIdx.y) {
        case 0: X = states; ldx = 400; Kreal = 400; chunks = 25;
                img = g_Wimg + O_A1; biasPad = g_ba1; dorelu = 1; Y = AH1; break;
        case 1: X = states; ldx = 400; Kreal = 400; chunks = 25;
                img = g_Wimg + O_SA; biasPad = nullptr; dorelu = 0; Y = AP; break;
        case 2: X = states; ldx = 400; Kreal = 400; chunks = 25;
                img = g_Wimg + O_SB; biasPad = nullptr; dorelu = 0; Y = BP; break;
        default: X = embeds; ldx = 300; Kreal = 300; chunks = 19;
                img = g_Wimg + O_SP; biasPad = nullptr; dorelu = 0; Y = PP; break;
    }
    const int M = T_TOK;
    const int tid  = threadIdx.x;
    const int lane = tid & 31;
    const int warp = tid >> 5;
    const int mw   = warp & 3;
    const int nw   = warp >> 2;
    const int m0   = blockIdx.x * 64;

    float acc[10][4];
#pragma unroll
    for (int t = 0; t < 10; t++)
#pragma unroll
        for (int j = 0; j < 4; j++) acc[t][j] = 0.f;

    const int aRow = (lane & 7) + ((lane & 8) ? 8 : 0);
    const unsigned aOff = (unsigned)((mw * 16 + aRow) * 80 + ((lane & 16) ? 16 : 0));
    const int bRow = (lane & 7) + ((lane & 16) ? 8 : 0);
    const unsigned bOff = (unsigned)(bRow * 80 + ((lane & 8) ? 16 : 0));
    const unsigned asBase = cvta_s(As);
    const unsigned bsBase = cvta_s(Bs);

    stage_A(X, ldx, Kreal, m0, M, 0, As, tid);
    stage_B(img, 0, Bs, tid);
    __syncthreads();

    for (int c = 0; c < chunks; c++) {
        int cur = c & 1;
        if (c + 1 < chunks) {
            stage_A(X, ldx, Kreal, m0, M, c + 1, As + (cur ^ 1) * 2560, tid);
            stage_B(img, c + 1, Bs + (cur ^ 1) * 6400, tid);
        }
        unsigned aBuf = asBase + cur * 5120;
        unsigned bBuf = bsBase + cur * 12800;
        MMA_CHUNK(aBuf, bBuf);
        __syncthreads();
    }

    const int r1 = m0 + mw * 16 + (lane >> 2);
    const int cBase = nw * 80 + 2 * (lane & 3);
#pragma unroll
    for (int t = 0; t < 10; t++) {
        int col = cBase + t * 8;
        float b0 = 0.f, b1v = 0.f;
        if (biasPad) { b0 = biasPad[col]; b1v = biasPad[col + 1]; }
        float2 vA = make_float2(acc[t][0] + b0, acc[t][1] + b1v);
        float2 vB = make_float2(acc[t][2] + b0, acc[t][3] + b1v);
        if (dorelu) {
            vA.x = fmaxf(vA.x, 0.f); vA.y = fmaxf(vA.y, 0.f);
            vB.x = fmaxf(vB.x, 0.f); vB.y = fmaxf(vB.y, 0.f);
        }
        if (r1 < M)     *(float2*)(Y + (size_t)r1 * LDO + col)       = vA;
        if (r1 + 8 < M) *(float2*)(Y + (size_t)(r1 + 8) * LDO + col) = vB;
    }
}

// ---------------- attn layer2 + fused logits ----------------
__global__ __launch_bounds__(256, 2) void attn2_k(
    const float* __restrict__ AH1, const float* __restrict__ ab3,
    float* __restrict__ LG)
{
    __shared__ __nv_bfloat16 As[2 * 64 * 40];
    __shared__ __nv_bfloat16 Bs[2 * 160 * 40];
    __shared__ float red2[128];

    const int tid  = threadIdx.x;
    const int lane = tid & 31;
    const int warp = tid >> 5;
    const int mw   = warp & 3;
    const int nw   = warp >> 2;
    const int m0   = blockIdx.x * 64;
    const int M    = T_TOK;
    const __nv_bfloat16* img = g_Wimg + O_A2;

    float acc[10][4];
#pragma unroll
    for (int t = 0; t < 10; t++)
#pragma unroll
        for (int j = 0; j < 4; j++) acc[t][j] = 0.f;

    const int aRow = (lane & 7) + ((lane & 8) ? 8 : 0);
    const unsigned aOff = (unsigned)((mw * 16 + aRow) * 80 + ((lane & 16) ? 16 : 0));
    const int bRow = (lane & 7) + ((lane & 16) ? 8 : 0);
    const unsigned bOff = (unsigned)(bRow * 80 + ((lane & 8) ? 16 : 0));
    const unsigned asBase = cvta_s(As);
    const unsigned bsBase = cvta_s(Bs);

    stage_A(AH1, LDO, 160, m0, M, 0, As, tid);
    stage_B(img, 0, Bs, tid);
    __syncthreads();

    for (int c = 0; c < 10; c++) {
        int cur = c & 1;
        if (c + 1 < 10) {
            stage_A(AH1, LDO, 160, m0, M, c + 1, As + (cur ^ 1) * 2560, tid);
            stage_B(img, c + 1, Bs + (cur ^ 1) * 6400, tid);
        }
        unsigned aBuf = asBase + cur * 5120;
        unsigned bBuf = bsBase + cur * 12800;
        MMA_CHUNK(aBuf, bBuf);
        __syncthreads();
    }

    // fused: logits = relu(H2 + ba2) . wa3
    const int cBase = nw * 80 + 2 * (lane & 3);
    float s1 = 0.f, s2 = 0.f;
#pragma unroll
    for (int t = 0; t < 10; t++) {
        int col = cBase + t * 8;
        float2 b2 = *(const float2*)(g_ba2 + col);
        float2 w3 = *(const float2*)(g_wa3 + col);
        s1 += fmaxf(acc[t][0] + b2.x, 0.f) * w3.x + fmaxf(acc[t][1] + b2.y, 0.f) * w3.y;
        s2 += fmaxf(acc[t][2] + b2.x, 0.f) * w3.x + fmaxf(acc[t][3] + b2.y, 0.f) * w3.y;
    }
    s1 += __shfl_xor_sync(0xffffffffu, s1, 1);
    s1 += __shfl_xor_sync(0xffffffffu, s1, 2);
    s2 += __shfl_xor_sync(0xffffffffu, s2, 1);
    s2 += __shfl_xor_sync(0xffffffffu, s2, 2);
    if ((lane & 3) == 0) {
        int row = mw * 16 + (lane >> 2);
        red2[row * 2 + nw]       = s1;
        red2[(row + 8) * 2 + nw] = s2;
    }
    __syncthreads();
    if (tid < 64) {
        int m = m0 + tid;
        if (m < M) LG[m] = red2[tid * 2] + red2[tid * 2 + 1] + ab3[0];
    }
}

// ---------------- persistent span kernel ----------------
// smem: W2s 128000 @0, H1s 51200 @128000, wgt 2560 @179200,
//       red 512 @181760, lgs 320 @182272  -> 182592 B
#define SPAN_SMEM 182592
#define N_UNITS 626   // 313 tiles x 2 width-halves

__global__ __launch_bounds__(256) void span_k(
    const float* __restrict__ AP, const float* __restrict__ BP,
    const float* __restrict__ PP, const float* __restrict__ LG,
    const float* __restrict__ b3, float* __restrict__ out)
{
    extern __shared__ char sm[];
    __nv_bfloat16* W2s = (__nv_bfloat16*)sm;
    __nv_bfloat16* H1s = (__nv_bfloat16*)(sm + 128000);
    float* wgt = (float*)(sm + 179200);
    float* red = (float*)(sm + 181760);
    float* lgs = (float*)(sm + 182272);
    __shared__ int s_u;

    const int tid  = threadIdx.x;
    const int lane = tid & 31;
    const int warp = tid >> 5;
    const int mw   = warp & 3;
    const int nw   = warp >> 2;

    const int aRow = (lane & 7) + ((lane & 8) ? 8 : 0);
    const unsigned aOff = (unsigned)((mw * 16 + aRow) * 80 + ((lane & 16) ? 16 : 0));
    const int bRow = (lane & 7) + ((lane & 16) ? 8 : 0);
    const unsigned bOff = (unsigned)(bRow * 80 + ((lane & 8) ? 16 : 0));
    const unsigned h1Base = cvta_s(H1s);
    const unsigned w2Base = cvta_s(W2s);

    // load full W2 image (10 chunks, 128 KB) once
    {
        const float4* src = (const float4*)(g_Wimg + O_W2);
        float4* dst = (float4*)W2s;
        for (int i = tid; i < 8000; i += 256) dst[i] = src[i];
    }

    while (true) {
        if (tid == 0) s_u = atomicAdd(&g_ctr, 1);
        __syncthreads();
        int u = s_u;
        if (u >= N_UNITS) break;
        int tile = u >> 1;
        int half = u & 1;
        int s0 = tile * 64;

        if (tid < 80) {
            int ix = s0 + tid;
            lgs[tid] = (ix < T_TOK) ? LG[ix] : 0.f;
        }
        __syncthreads();

        for (int n = 1 + half * 5; n < 6 + half * 5; n++) {
            const int S = T_TOK - n + 1;

            if (tid < 64) {
                int s = s0 + tid;
                if (s < S) {
                    float mx = -1e30f;
                    for (int j = 0; j < n; j++) mx = fmaxf(mx, lgs[tid + j]);
                    float sum = 0.f;
                    for (int j = 0; j < n; j++) {
                        float e = __expf(lgs[tid + j] - mx);
                        wgt[tid * 10 + j] = e;
                        sum += e;
                    }
                    float inv = 1.f / sum;
                    for (int j = 0; j < n; j++) wgt[tid * 10 + j] *= inv;
                }
            }
            __syncthreads();

            // stage A: H1 = relu(AP[s] + BP[e] + b1 + sum_j w_j PP[s+j]) -> hi/lo
#pragma unroll
            for (int it = 0; it < 10; it++) {
                int idx = tid + it * 256;
                int i = idx / 40;
                int g = idx - i * 40;
                int s = s0 + i;
                float4 v = make_float4(0.f, 0.f, 0.f, 0.f);
                if (s < S) {
                    int c0 = g * 4;
                    float4 a4 = *(const float4*)(AP + (size_t)s * LDO + c0);
                    float4 q4 = *(const float4*)(BP + (size_t)(s + n - 1) * LDO + c0);
                    float4 b4 = *(const float4*)(g_b1 + c0);
                    v.x = a4.x + q4.x + b4.x;
                    v.y = a4.y + q4.y + b4.y;
                    v.z = a4.z + q4.z + b4.z;
                    v.w = a4.w + q4.w + b4.w;
                    for (int j = 0; j < n; j++) {
                        float w = wgt[i * 10 + j];
                        float4 p4 = *(const float4*)(PP + (size_t)(s + j) * LDO + c0);
                        v.x += w * p4.x; v.y += w * p4.y;
                        v.z += w * p4.z; v.w += w * p4.w;
                    }
                    v.x = fmaxf(v.x, 0.f); v.y = fmaxf(v.y, 0.f);
                    v.z = fmaxf(v.z, 0.f); v.w = fmaxf(v.w, 0.f);
                }
                unsigned short h[4], l[4];
                split_bf16(v.x, h[0], l[0]); split_bf16(v.y, h[1], l[1]);
                split_bf16(v.z, h[2], l[2]); split_bf16(v.w, h[3], l[3]);
                int cch = g >> 2, kk = (g & 3) * 4;
                unsigned short* dst = (unsigned short*)(H1s + (size_t)(cch * 64 + i) * 40 + kk);
                *(uint2*)dst        = make_uint2((unsigned)h[0] | ((unsigned)h[1] << 16),
                                                 (unsigned)h[2] | ((unsigned)h[3] << 16));
                *(uint2*)(dst + 16) = make_uint2((unsigned)l[0] | ((unsigned)l[1] << 16),
                                                 (unsigned)l[2] | ((unsigned)l[3] << 16));
            }
            __syncthreads();

            // MMA: W2 resident, H1 resident -> no staging, no inner syncs
            float acc[10][4];
#pragma unroll
            for (int t = 0; t < 10; t++)
#pragma unroll
                for (int j = 0; j < 4; j++) acc[t][j] = 0.f;
#pragma unroll
            for (int c = 0; c < 10; c++) {
                unsigned aBuf = h1Base + (unsigned)(c * 5120);
                unsigned bBuf = w2Base + (unsigned)(c * 12800);
                MMA_CHUNK(aBuf, bBuf);
            }

            // epilogue: relu(H2 + b2) . w3, reduce
            const int cBase = nw * 80 + 2 * (lane & 3);
            float s1 = 0.f, s2 = 0.f;
#pragma unroll
            for (int t = 0; t < 10; t++) {
                int col = cBase + t * 8;
                float2 w3 = *(const float2*)(g_w3 + col);
                float2 b2 = *(const float2*)(g_b2 + col);
                s1 += fmaxf(acc[t][0] + b2.x, 0.f) * w3.x + fmaxf(acc[t][1] + b2.y, 0.f) * w3.y;
                s2 += fmaxf(acc[t][2] + b2.x, 0.f) * w3.x + fmaxf(acc[t][3] + b2.y, 0.f) * w3.y;
            }
            s1 += __shfl_xor_sync(0xffffffffu, s1, 1);
            s1 += __shfl_xor_sync(0xffffffffu, s1, 2);
            s2 += __shfl_xor_sync(0xffffffffu, s2, 1);
            s2 += __shfl_xor_sync(0xffffffffu, s2, 2);
            if ((lane & 3) == 0) {
                int row = mw * 16 + (lane >> 2);
                red[row * 2 + nw]       = s1;
                red[(row + 8) * 2 + nw] = s2;
            }
            __syncthreads();

            if (tid < 64) {
                int s = s0 + tid;
                if (s < S) {
                    long long off = (long long)(n - 1) * (T_TOK + 1)
                                  - (long long)(n - 1) * n / 2;
                    out[off + s] = red[tid * 2] + red[tid * 2 + 1] + b3[0];
                }
            }
            __syncthreads();
        }
    }
}

// ---------------- host ----------------
extern "C" void kernel_launch(void* const* d_in, const int* in_sizes, int n_in,
                              void* d_out, int out_size)
{
    const float* embeds  = (const float*)d_in[0];
    const float* states  = (const float*)d_in[1];
    const float* attn_W1 = (const float*)d_in[2];
    const float* attn_b1 = (const float*)d_in[3];
    const float* attn_W2 = (const float*)d_in[4];
    const float* attn_b2 = (const float*)d_in[5];
    const float* attn_W3 = (const float*)d_in[6];
    const float* attn_b3 = (const float*)d_in[7];
    const float* sc_W1   = (const float*)d_in[8];
    const float* sc_b1   = (const float*)d_in[9];
    const float* sc_W2   = (const float*)d_in[10];
    const float* sc_b2   = (const float*)d_in[11];
    const float* sc_W3   = (const float*)d_in[12];
    const float* sc_b3   = (const float*)d_in[13];
    float* out = (float*)d_out;

    float *AH1, *AP, *BP, *PP, *LG;
    cudaGetSymbolAddress((void**)&AH1, g_AH1);
    cudaGetSymbolAddress((void**)&AP,  g_AP);
    cudaGetSymbolAddress((void**)&BP,  g_BP);
    cudaGetSymbolAddress((void**)&PP,  g_PP);
    cudaGetSymbolAddress((void**)&LG,  g_LG);

    const int gm = (T_TOK + 63) / 64;  // 313

    prep_all<<<148, 256>>>(attn_W1, sc_W1, attn_W2, sc_W2,
                           attn_b1, attn_b2, sc_b1, sc_b2, sc_W3, attn_W3);

    gemmA<<<dim3(gm, 4), 256>>>(states, embeds, AH1, AP, BP, PP);

    attn2_k<<<gm, 256>>>(AH1, attn_b3, LG);

    cudaFuncSetAttribute(span_k, cudaFuncAttributeMaxDynamicSharedMemorySize, SPAN_SMEM);
    span_k<<<148, 256, SPAN_SMEM>>>(AP, BP, PP, LG, sc_b3, out);
}

// round 6
// speedup vs baseline: 2.8090x; 1.1171x over previous
#include <cuda_runtime.h>
#include <cuda_bf16.h>

#define T_TOK 20000
#define LDO   160

// ---------------- scratch ----------------
__device__ __align__(256) float g_AH1[T_TOK * LDO];
__device__ __align__(256) float g_AP [T_TOK * LDO];
__device__ __align__(256) float g_BP [T_TOK * LDO];
__device__ __align__(256) float g_PP [(T_TOK + 64) * LDO];  // 64 zero pad rows
__device__ __align__(256) float g_LG [T_TOK];
__device__ int g_ctr;
__device__ unsigned g_maxbits;

// weight images: per k16-chunk: 160 rows(n) x 40 bf16 (16 hi | 16 lo | 8 pad)
// global chunk order: attn1:25, scA:25, scB:25, scP:19, attn2:10, W2:10 -> 114
#define CH_ELEMS 6400
#define O_A1 0
#define O_SA (25 * CH_ELEMS)
#define O_SB (50 * CH_ELEMS)
#define O_SP (75 * CH_ELEMS)
#define O_A2 (94 * CH_ELEMS)
#define O_W2 (104 * CH_ELEMS)
__device__ __align__(256) __nv_bfloat16 g_Wimg[114 * CH_ELEMS];

__device__ __align__(256) float g_ba1[160];
__device__ __align__(256) float g_ba2[160];
__device__ __align__(256) float g_b1 [160];
__device__ __align__(256) float g_b2 [160];
__device__ __align__(256) float g_w3 [160];
__device__ __align__(256) float g_wa3[160];

// ---------------- helpers ----------------
__device__ __forceinline__ unsigned cvta_s(const void* p) {
    return (unsigned)__cvta_generic_to_shared(p);
}
__device__ __forceinline__ void ldmx4(unsigned* r, unsigned addr) {
    asm volatile("ldmatrix.sync.aligned.m8n8.x4.shared.b16 {%0,%1,%2,%3}, [%4];"
        : "=r"(r[0]), "=r"(r[1]), "=r"(r[2]), "=r"(r[3]) : "r"(addr));
}
__device__ __forceinline__ void mma16816(float* d, const unsigned* a, const unsigned* b) {
    asm volatile(
        "mma.sync.aligned.m16n8k16.row.col.f32.bf16.bf16.f32 "
        "{%0,%1,%2,%3}, {%4,%5,%6,%7}, {%8,%9}, {%0,%1,%2,%3};"
        : "+f"(d[0]), "+f"(d[1]), "+f"(d[2]), "+f"(d[3])
        : "r"(a[0]), "r"(a[1]), "r"(a[2]), "r"(a[3]), "r"(b[0]), "r"(b[1]));
}
__device__ __forceinline__ void split_bf16(float v, unsigned short& h, unsigned short& l) {
    __nv_bfloat16 hb = __float2bfloat16_rn(v);
    __nv_bfloat16 lb = __float2bfloat16_rn(v - __bfloat162float(hb));
    h = __bfloat16_as_ushort(hb);
    l = __bfloat16_as_ushort(lb);
}
__device__ __forceinline__ unsigned encf(float x) {
    unsigned u = __float_as_uint(x);
    return (u & 0x80000000u) ? ~u : (u | 0x80000000u);
}
__device__ __forceinline__ float decf(unsigned u) {
    unsigned b = (u & 0x80000000u) ? (u & 0x7fffffffu) : ~u;
    return __uint_as_float(b);
}

// ---------------- single fused prep ----------------
__global__ void prep_all(const float* __restrict__ aW1, const float* __restrict__ scW1,
                         const float* __restrict__ aW2, const float* __restrict__ scW2,
                         const float* __restrict__ ab1, const float* __restrict__ ab2,
                         const float* __restrict__ sb1, const float* __restrict__ sb2,
                         const float* __restrict__ sW3, const float* __restrict__ aW3)
{
    int tid = threadIdx.x;
    if (blockIdx.x == 0) {
        if (tid < 160) {
            bool ok = tid < 150;
            g_ba1[tid] = ok ? ab1[tid] : 0.f;
            g_ba2[tid] = ok ? ab2[tid] : 0.f;
            g_b1 [tid] = ok ? sb1[tid] : 0.f;
            g_b2 [tid] = ok ? sb2[tid] : 0.f;
            g_w3 [tid] = ok ? sW3[tid] : 0.f;
            g_wa3[tid] = ok ? aW3[tid] : 0.f;
        }
        if (tid == 0) { g_ctr = 0; g_maxbits = 0u; }
    }
    const int total = 114 * 2560;
    for (int idx = blockIdx.x * blockDim.x + tid; idx < total;
         idx += gridDim.x * blockDim.x) {
        int c   = idx / 2560;
        int rem = idx - c * 2560;
        int nn  = rem >> 4;
        int kk  = rem & 15;
        const float* W; int K; int lc;
        if      (c < 25)  { W = aW1;             K = 400; lc = c;       }
        else if (c < 50)  { W = scW1;            K = 400; lc = c - 25;  }
        else if (c < 75)  { W = scW1 + 400*150;  K = 400; lc = c - 50;  }
        else if (c < 94)  { W = scW1 + 800*150;  K = 300; lc = c - 75;  }
        else if (c < 104) { W = aW2;             K = 150; lc = c - 94;  }
        else              { W = scW2;            K = 150; lc = c - 104; }
        int k = lc * 16 + kk;
        float v = (k < K && nn < 150) ? W[k * 150 + nn] : 0.f;
        unsigned short h, l;
        split_bf16(v, h, l);
        unsigned short* dst = (unsigned short*)(g_Wimg + (size_t)c * CH_ELEMS + nn * 40);
        dst[kk]      = h;
        dst[16 + kk] = l;
        if (kk < 8) dst[32 + kk] = 0;
    }
}

// ---------------- staging helpers ----------------
__device__ __forceinline__ void stage_A(const float* __restrict__ X, int ldx,
                                        int Kreal, int m0, int M, int c,
                                        __nv_bfloat16* __restrict__ Abuf, int tid)
{
    int r  = tid >> 2;
    int kq = tid & 3;
    int m  = m0 + r;
    int k0 = c * 16 + kq * 4;
    float4 v = make_float4(0.f, 0.f, 0.f, 0.f);
    if (m < M) {
        if (k0 + 3 < Kreal) {
            v = *(const float4*)(X + (size_t)m * ldx + k0);
        } else {
            float* pv = (float*)&v;
            for (int j = 0; j < 4; j++)
                if (k0 + j < Kreal) pv[j] = X[(size_t)m * ldx + k0 + j];
        }
    }
    unsigned short h[4], l[4];
    split_bf16(v.x, h[0], l[0]); split_bf16(v.y, h[1], l[1]);
    split_bf16(v.z, h[2], l[2]); split_bf16(v.w, h[3], l[3]);
    unsigned short* dst = (unsigned short*)(Abuf + r * 40 + kq * 4);
    *(uint2*)dst        = make_uint2((unsigned)h[0] | ((unsigned)h[1] << 16),
                                     (unsigned)h[2] | ((unsigned)h[3] << 16));
    *(uint2*)(dst + 16) = make_uint2((unsigned)l[0] | ((unsigned)l[1] << 16),
                                     (unsigned)l[2] | ((unsigned)l[3] << 16));
}

__device__ __forceinline__ void stage_B(const __nv_bfloat16* __restrict__ img, int c,
                                        __nv_bfloat16* __restrict__ Bbuf, int tid)
{
    const float4* src = (const float4*)(img + (size_t)c * CH_ELEMS);
    float4* dst = (float4*)Bbuf;
    for (int i = tid; i < 800; i += 256) dst[i] = src[i];
}

// ---------------- core MMA tile macro-body ----------------
#define MMA_CHUNK(aBuf, bBuf)                                                   \
    {                                                                           \
        unsigned ah[4], al[4];                                                  \
        ldmx4(ah, (aBuf) + aOff);                                               \
        ldmx4(al, (aBuf) + aOff + 32);                                          \
        _Pragma("unroll")                                                       \
        for (int p = 0; p < 5; p++) {                                           \
            unsigned bh[4], bl[4];                                              \
            unsigned baddr = (bBuf) + (unsigned)((nw * 80 + p * 16) * 80) + bOff; \
            ldmx4(bh, baddr);                                                   \
            ldmx4(bl, baddr + 32);                                              \
            mma16816(acc[2 * p],     ah, bh);                                   \
            mma16816(acc[2 * p],     ah, bl);                                   \
            mma16816(acc[2 * p],     al, bh);                                   \
            mma16816(acc[2 * p + 1], ah, bh + 2);                               \
            mma16816(acc[2 * p + 1], ah, bl + 2);                               \
            mma16816(acc[2 * p + 1], al, bh + 2);                               \
        }                                                                       \
    }

// ---------------- batched GEMM: 4 independent jobs via blockIdx.y ----------------
__global__ __launch_bounds__(256, 2) void gemmA(
    const float* __restrict__ states, const float* __restrict__ embeds,
    float* __restrict__ AH1, float* __restrict__ AP,
    float* __restrict__ BP,  float* __restrict__ PP)
{
    __shared__ __nv_bfloat16 As[2 * 64 * 40];
    __shared__ __nv_bfloat16 Bs[2 * 160 * 40];

    const float* X; int ldx, Kreal, chunks; const __nv_bfloat16* img;
    const float* biasPad; int dorelu; float* Y;
    switch (blockIdx.y) {
        case 0: X = states; ldx = 400; Kreal = 400; chunks = 25;
                img = g_Wimg + O_A1; biasPad = g_ba1; dorelu = 1; Y = AH1; break;
        case 1: X = states; ldx = 400; Kreal = 400; chunks = 25;
                img = g_Wimg + O_SA; biasPad = nullptr; dorelu = 0; Y = AP; break;
        case 2: X = states; ldx = 400; Kreal = 400; chunks = 25;
                img = g_Wimg + O_SB; biasPad = nullptr; dorelu = 0; Y = BP; break;
        default: X = embeds; ldx = 300; Kreal = 300; chunks = 19;
                img = g_Wimg + O_SP; biasPad = nullptr; dorelu = 0; Y = PP; break;
    }
    const int M = T_TOK;
    const int tid  = threadIdx.x;
    const int lane = tid & 31;
    const int warp = tid >> 5;
    const int mw   = warp & 3;
    const int nw   = warp >> 2;
    const int m0   = blockIdx.x * 64;

    float acc[10][4];
#pragma unroll
    for (int t = 0; t < 10; t++)
#pragma unroll
        for (int j = 0; j < 4; j++) acc[t][j] = 0.f;

    const int aRow = (lane & 7) + ((lane & 8) ? 8 : 0);
    const unsigned aOff = (unsigned)((mw * 16 + aRow) * 80 + ((lane & 16) ? 16 : 0));
    const int bRow = (lane & 7) + ((lane & 16) ? 8 : 0);
    const unsigned bOff = (unsigned)(bRow * 80 + ((lane & 8) ? 16 : 0));
    const unsigned asBase = cvta_s(As);
    const unsigned bsBase = cvta_s(Bs);

    stage_A(X, ldx, Kreal, m0, M, 0, As, tid);
    stage_B(img, 0, Bs, tid);
    __syncthreads();

    for (int c = 0; c < chunks; c++) {
        int cur = c & 1;
        if (c + 1 < chunks) {
            stage_A(X, ldx, Kreal, m0, M, c + 1, As + (cur ^ 1) * 2560, tid);
            stage_B(img, c + 1, Bs + (cur ^ 1) * 6400, tid);
        }
        unsigned aBuf = asBase + cur * 5120;
        unsigned bBuf = bsBase + cur * 12800;
        MMA_CHUNK(aBuf, bBuf);
        __syncthreads();
    }

    const int r1 = m0 + mw * 16 + (lane >> 2);
    const int cBase = nw * 80 + 2 * (lane & 3);
#pragma unroll
    for (int t = 0; t < 10; t++) {
        int col = cBase + t * 8;
        float b0 = 0.f, b1v = 0.f;
        if (biasPad) { b0 = biasPad[col]; b1v = biasPad[col + 1]; }
        float2 vA = make_float2(acc[t][0] + b0, acc[t][1] + b1v);
        float2 vB = make_float2(acc[t][2] + b0, acc[t][3] + b1v);
        if (dorelu) {
            vA.x = fmaxf(vA.x, 0.f); vA.y = fmaxf(vA.y, 0.f);
            vB.x = fmaxf(vB.x, 0.f); vB.y = fmaxf(vB.y, 0.f);
        }
        if (r1 < M)     *(float2*)(Y + (size_t)r1 * LDO + col)       = vA;
        if (r1 + 8 < M) *(float2*)(Y + (size_t)(r1 + 8) * LDO + col) = vB;
    }
}

// ---------------- attn layer2 + fused logits + global max ----------------
__global__ __launch_bounds__(256, 2) void attn2_k(
    const float* __restrict__ AH1, const float* __restrict__ ab3,
    float* __restrict__ LG)
{
    __shared__ __nv_bfloat16 As[2 * 64 * 40];
    __shared__ __nv_bfloat16 Bs[2 * 160 * 40];
    __shared__ float red2[128];
    __shared__ float bmax[2];

    const int tid  = threadIdx.x;
    const int lane = tid & 31;
    const int warp = tid >> 5;
    const int mw   = warp & 3;
    const int nw   = warp >> 2;
    const int m0   = blockIdx.x * 64;
    const int M    = T_TOK;
    const __nv_bfloat16* img = g_Wimg + O_A2;

    float acc[10][4];
#pragma unroll
    for (int t = 0; t < 10; t++)
#pragma unroll
        for (int j = 0; j < 4; j++) acc[t][j] = 0.f;

    const int aRow = (lane & 7) + ((lane & 8) ? 8 : 0);
    const unsigned aOff = (unsigned)((mw * 16 + aRow) * 80 + ((lane & 16) ? 16 : 0));
    const int bRow = (lane & 7) + ((lane & 16) ? 8 : 0);
    const unsigned bOff = (unsigned)(bRow * 80 + ((lane & 8) ? 16 : 0));
    const unsigned asBase = cvta_s(As);
    const unsigned bsBase = cvta_s(Bs);

    stage_A(AH1, LDO, 160, m0, M, 0, As, tid);
    stage_B(img, 0, Bs, tid);
    __syncthreads();

    for (int c = 0; c < 10; c++) {
        int cur = c & 1;
        if (c + 1 < 10) {
            stage_A(AH1, LDO, 160, m0, M, c + 1, As + (cur ^ 1) * 2560, tid);
            stage_B(img, c + 1, Bs + (cur ^ 1) * 6400, tid);
        }
        unsigned aBuf = asBase + cur * 5120;
        unsigned bBuf = bsBase + cur * 12800;
        MMA_CHUNK(aBuf, bBuf);
        __syncthreads();
    }

    // fused: logits = relu(H2 + ba2) . wa3
    const int cBase = nw * 80 + 2 * (lane & 3);
    float s1 = 0.f, s2 = 0.f;
#pragma unroll
    for (int t = 0; t < 10; t++) {
        int col = cBase + t * 8;
        float2 b2 = *(const float2*)(g_ba2 + col);
        float2 w3 = *(const float2*)(g_wa3 + col);
        s1 += fmaxf(acc[t][0] + b2.x, 0.f) * w3.x + fmaxf(acc[t][1] + b2.y, 0.f) * w3.y;
        s2 += fmaxf(acc[t][2] + b2.x, 0.f) * w3.x + fmaxf(acc[t][3] + b2.y, 0.f) * w3.y;
    }
    s1 += __shfl_xor_sync(0xffffffffu, s1, 1);
    s1 += __shfl_xor_sync(0xffffffffu, s1, 2);
    s2 += __shfl_xor_sync(0xffffffffu, s2, 1);
    s2 += __shfl_xor_sync(0xffffffffu, s2, 2);
    if ((lane & 3) == 0) {
        int row = mw * 16 + (lane >> 2);
        red2[row * 2 + nw]       = s1;
        red2[(row + 8) * 2 + nw] = s2;
    }
    __syncthreads();
    if (tid < 64) {
        int m = m0 + tid;
        float v = red2[tid * 2] + red2[tid * 2 + 1] + ab3[0];
        float mv = -3.4e38f;
        if (m < M) { LG[m] = v; mv = v; }
#pragma unroll
        for (int o = 16; o; o >>= 1) mv = fmaxf(mv, __shfl_xor_sync(0xffffffffu, mv, o));
        if ((tid & 31) == 0) bmax[tid >> 5] = mv;
    }
    __syncthreads();
    if (tid == 0) atomicMax(&g_maxbits, encf(fmaxf(bmax[0], bmax[1])));
}

// ---------------- persistent span kernel (incremental softmax pooling) ----------------
// smem bytes: W2s 128000 @0, H1s 51200 @128000, NS 40960 @179200,
//             eg 320 @220160, sD 256 @220480, invD 256 @220736, red 512 @220992
#define SPAN_SMEM 221504
#define N_UNITS 626   // 313 tiles x 2 width-halves

__global__ __launch_bounds__(256) void span_k(
    const float* __restrict__ AP, const float* __restrict__ BP,
    const float* __restrict__ PP, const float* __restrict__ LG,
    const float* __restrict__ b3, float* __restrict__ out)
{
    extern __shared__ char sm[];
    __nv_bfloat16* W2s = (__nv_bfloat16*)sm;
    __nv_bfloat16* H1s = (__nv_bfloat16*)(sm + 128000);
    float* NS   = (float*)(sm + 179200);
    float* eg   = (float*)(sm + 220160);
    float* sD   = (float*)(sm + 220480);
    float* invD = (float*)(sm + 220736);
    float* red  = (float*)(sm + 220992);
    __shared__ int s_u;

    const int tid  = threadIdx.x;
    const int lane = tid & 31;
    const int warp = tid >> 5;
    const int mw   = warp & 3;
    const int nw   = warp >> 2;

    const int aRow = (lane & 7) + ((lane & 8) ? 8 : 0);
    const unsigned aOff = (unsigned)((mw * 16 + aRow) * 80 + ((lane & 16) ? 16 : 0));
    const int bRow = (lane & 7) + ((lane & 16) ? 8 : 0);
    const unsigned bOff = (unsigned)(bRow * 80 + ((lane & 8) ? 16 : 0));
    const unsigned h1Base = cvta_s(H1s);
    const unsigned w2Base = cvta_s(W2s);

    // load full W2 image (128 KB) once
    {
        const float4* src = (const float4*)(g_Wimg + O_W2);
        float4* dst = (float4*)W2s;
        for (int i = tid; i < 8000; i += 256) dst[i] = src[i];
    }

    const float Mx = decf(g_maxbits);

    while (true) {
        if (tid == 0) s_u = atomicAdd(&g_ctr, 1);
        __syncthreads();
        int u = s_u;
        if (u >= N_UNITS) break;
        int tile = u >> 1;
        int half = u & 1;
        int s0 = tile * 64;
        int n0 = 1 + half * 5;

        if (tid < 80) {
            int t = s0 + tid;
            eg[tid] = (t < T_TOK) ? __expf(LG[t] - Mx) : 0.f;
        }
        __syncthreads();

        // init NS (numerator for width n0) and sD/invD
#pragma unroll
        for (int it = 0; it < 10; it++) {
            int idx = tid + it * 256;
            int i = idx / 40, g = idx - i * 40, c0 = g * 4;
            float4 a = make_float4(0.f, 0.f, 0.f, 0.f);
            for (int j = 0; j < n0; j++) {
                float e = eg[i + j];
                float4 p = *(const float4*)(PP + (size_t)(s0 + i + j) * LDO + c0);
                a.x += e * p.x; a.y += e * p.y;
                a.z += e * p.z; a.w += e * p.w;
            }
            *(float4*)(NS + i * 160 + c0) = a;
        }
        if (tid < 64) {
            float d = 0.f;
            for (int j = 0; j < n0; j++) d += eg[tid + j];
            sD[tid] = d;
            invD[tid] = 1.f / d;
        }
        __syncthreads();

        for (int n = n0; n < n0 + 5; n++) {
            const int S = T_TOK - n + 1;

            // build H1 = relu(AP[s] + BP[s+n-1] + b1 + NS*invD) -> hi/lo split
#pragma unroll
            for (int it = 0; it < 10; it++) {
                int idx = tid + it * 256;
                int i = idx / 40, g = idx - i * 40, c0 = g * 4;
                int s = s0 + i;
                float4 v = make_float4(0.f, 0.f, 0.f, 0.f);
                if (s < S) {
                    float4 a4 = *(const float4*)(AP + (size_t)s * LDO + c0);
                    float4 q4 = *(const float4*)(BP + (size_t)(s + n - 1) * LDO + c0);
                    float4 b4 = *(const float4*)(g_b1 + c0);
                    float4 ns = *(const float4*)(NS + i * 160 + c0);
                    float id = invD[i];
                    v.x = fmaxf(a4.x + q4.x + b4.x + ns.x * id, 0.f);
                    v.y = fmaxf(a4.y + q4.y + b4.y + ns.y * id, 0.f);
                    v.z = fmaxf(a4.z + q4.z + b4.z + ns.z * id, 0.f);
                    v.w = fmaxf(a4.w + q4.w + b4.w + ns.w * id, 0.f);
                }
                unsigned short h[4], l[4];
                split_bf16(v.x, h[0], l[0]); split_bf16(v.y, h[1], l[1]);
                split_bf16(v.z, h[2], l[2]); split_bf16(v.w, h[3], l[3]);
                int cch = g >> 2, kk = (g & 3) * 4;
                unsigned short* dst = (unsigned short*)(H1s + (size_t)(cch * 64 + i) * 40 + kk);
                *(uint2*)dst        = make_uint2((unsigned)h[0] | ((unsigned)h[1] << 16),
                                                 (unsigned)h[2] | ((unsigned)h[3] << 16));
                *(uint2*)(dst + 16) = make_uint2((unsigned)l[0] | ((unsigned)l[1] << 16),
                                                 (unsigned)l[2] | ((unsigned)l[3] << 16));
            }
            __syncthreads();

            // MMA: W2 and H1 resident
            float acc[10][4];
#pragma unroll
            for (int t = 0; t < 10; t++)
#pragma unroll
                for (int j = 0; j < 4; j++) acc[t][j] = 0.f;
#pragma unroll
            for (int c = 0; c < 10; c++) {
                unsigned aBuf = h1Base + (unsigned)(c * 5120);
                unsigned bBuf = w2Base + (unsigned)(c * 12800);
                MMA_CHUNK(aBuf, bBuf);
            }

            // epilogue: relu(H2 + b2) . w3, reduce
            const int cBase = nw * 80 + 2 * (lane & 3);
            float s1 = 0.f, s2 = 0.f;
#pragma unroll
            for (int t = 0; t < 10; t++) {
                int col = cBase + t * 8;
                float2 w3 = *(const float2*)(g_w3 + col);
                float2 b2 = *(const float2*)(g_b2 + col);
                s1 += fmaxf(acc[t][0] + b2.x, 0.f) * w3.x + fmaxf(acc[t][1] + b2.y, 0.f) * w3.y;
                s2 += fmaxf(acc[t][2] + b2.x, 0.f) * w3.x + fmaxf(acc[t][3] + b2.y, 0.f) * w3.y;
            }
            s1 += __shfl_xor_sync(0xffffffffu, s1, 1);
            s1 += __shfl_xor_sync(0xffffffffu, s1, 2);
            s2 += __shfl_xor_sync(0xffffffffu, s2, 1);
            s2 += __shfl_xor_sync(0xffffffffu, s2, 2);
            if ((lane & 3) == 0) {
                int row = mw * 16 + (lane >> 2);
                red[row * 2 + nw]       = s1;
                red[(row + 8) * 2 + nw] = s2;
            }
            __syncthreads();

            if (tid < 64) {
                int s = s0 + tid;
                if (s < S) {
                    long long off = (long long)(n - 1) * (T_TOK + 1)
                                  - (long long)(n - 1) * n / 2;
                    out[off + s] = red[tid * 2] + red[tid * 2 + 1] + b3[0];
                }
            }

            // incremental update for next width: NS += eg*PP row, D += eg
            if (n < n0 + 4) {
#pragma unroll
                for (int it = 0; it < 10; it++) {
                    int idx = tid + it * 256;
                    int i = idx / 40, g = idx - i * 40, c0 = g * 4;
                    float e = eg[i + n];
                    float4 p = *(const float4*)(PP + (size_t)(s0 + i + n) * LDO + c0);
                    float4 ns = *(const float4*)(NS + i * 160 + c0);
                    ns.x += e * p.x; ns.y += e * p.y;
                    ns.z += e * p.z; ns.w += e * p.w;
                    *(float4*)(NS + i * 160 + c0) = ns;
                }
                if (tid < 64) {
                    sD[tid] += eg[tid + n];
                    invD[tid] = 1.f / sD[tid];
                }
            }
            __syncthreads();
        }
    }
}

// ---------------- host ----------------
extern "C" void kernel_launch(void* const* d_in, const int* in_sizes, int n_in,
                              void* d_out, int out_size)
{
    const float* embeds  = (const float*)d_in[0];
    const float* states  = (const float*)d_in[1];
    const float* attn_W1 = (const float*)d_in[2];
    const float* attn_b1 = (const float*)d_in[3];
    const float* attn_W2 = (const float*)d_in[4];
    const float* attn_b2 = (const float*)d_in[5];
    const float* attn_W3 = (const float*)d_in[6];
    const float* attn_b3 = (const float*)d_in[7];
    const float* sc_W1   = (const float*)d_in[8];
    const float* sc_b1   = (const float*)d_in[9];
    const float* sc_W2   = (const float*)d_in[10];
    const float* sc_b2   = (const float*)d_in[11];
    const float* sc_W3   = (const float*)d_in[12];
    const float* sc_b3   = (const float*)d_in[13];
    float* out = (float*)d_out;

    float *AH1, *AP, *BP, *PP, *LG;
    cudaGetSymbolAddress((void**)&AH1, g_AH1);
    cudaGetSymbolAddress((void**)&AP,  g_AP);
    cudaGetSymbolAddress((void**)&BP,  g_BP);
    cudaGetSymbolAddress((void**)&PP,  g_PP);
    cudaGetSymbolAddress((void**)&LG,  g_LG);

    const int gm = (T_TOK + 63) / 64;  // 313

    prep_all<<<148, 256>>>(attn_W1, sc_W1, attn_W2, sc_W2,
                           attn_b1, attn_b2, sc_b1, sc_b2, sc_W3, attn_W3);

    gemmA<<<dim3(gm, 4), 256>>>(states, embeds, AH1, AP, BP, PP);

    attn2_k<<<gm, 256>>>(AH1, attn_b3, LG);

    cudaFuncSetAttribute(span_k, cudaFuncAttributeMaxDynamicSharedMemorySize, SPAN_SMEM);
    span_k<<<148, 256, SPAN_SMEM>>>(AP, BP, PP, LG, sc_b3, out);
}

// round 8
// speedup vs baseline: 3.1132x; 1.1083x over previous
#include <cuda_runtime.h>
#include <cuda_bf16.h>

#define T_TOK 20000
#define LDO   160

// ---------------- scratch ----------------
__device__ __align__(256) float g_AH1[T_TOK * LDO];
__device__ __align__(256) float g_AP [T_TOK * LDO];
__device__ __align__(256) float g_BP [T_TOK * LDO];
__device__ __align__(256) float g_PP [(T_TOK + 64) * LDO];  // 64 zero pad rows
__device__ __align__(256) float g_LG [T_TOK];
__device__ int g_ctr;
__device__ unsigned g_maxbits;

// weight images: per k16-chunk: 160 rows(n) x 40 bf16 (16 hi | 16 lo | 8 pad)
#define CH_ELEMS 6400
#define O_A1 0
#define O_SA (25 * CH_ELEMS)
#define O_SB (50 * CH_ELEMS)
#define O_SP (75 * CH_ELEMS)
#define O_A2 (94 * CH_ELEMS)
#define O_W2 (104 * CH_ELEMS)
__device__ __align__(256) __nv_bfloat16 g_Wimg[114 * CH_ELEMS];

__device__ __align__(256) float g_ba1[160];
__device__ __align__(256) float g_ba2[160];
__device__ __align__(256) float g_b1 [160];
__device__ __align__(256) float g_b2 [160];
__device__ __align__(256) float g_w3 [160];
__device__ __align__(256) float g_wa3[160];

// ---------------- helpers ----------------
__device__ __forceinline__ unsigned cvta_s(const void* p) {
    return (unsigned)__cvta_generic_to_shared(p);
}
__device__ __forceinline__ void ldmx4(unsigned* r, unsigned addr) {
    asm volatile("ldmatrix.sync.aligned.m8n8.x4.shared.b16 {%0,%1,%2,%3}, [%4];"
        : "=r"(r[0]), "=r"(r[1]), "=r"(r[2]), "=r"(r[3]) : "r"(addr));
}
__device__ __forceinline__ void ldmx2(unsigned* r, unsigned addr) {
    asm volatile("ldmatrix.sync.aligned.m8n8.x2.shared.b16 {%0,%1}, [%2];"
        : "=r"(r[0]), "=r"(r[1]) : "r"(addr));
}
__device__ __forceinline__ void mma16816(float* d, const unsigned* a, const unsigned* b) {
    asm volatile(
        "mma.sync.aligned.m16n8k16.row.col.f32.bf16.bf16.f32 "
        "{%0,%1,%2,%3}, {%4,%5,%6,%7}, {%8,%9}, {%0,%1,%2,%3};"
        : "+f"(d[0]), "+f"(d[1]), "+f"(d[2]), "+f"(d[3])
        : "r"(a[0]), "r"(a[1]), "r"(a[2]), "r"(a[3]), "r"(b[0]), "r"(b[1]));
}
__device__ __forceinline__ void split_bf16(float v, unsigned short& h, unsigned short& l) {
    __nv_bfloat16 hb = __float2bfloat16_rn(v);
    __nv_bfloat16 lb = __float2bfloat16_rn(v - __bfloat162float(hb));
    h = __bfloat16_as_ushort(hb);
    l = __bfloat16_as_ushort(lb);
}
__device__ __forceinline__ unsigned encf(float x) {
    unsigned u = __float_as_uint(x);
    return (u & 0x80000000u) ? ~u : (u | 0x80000000u);
}
__device__ __forceinline__ float decf(unsigned u) {
    unsigned b = (u & 0x80000000u) ? (u & 0x7fffffffu) : ~u;
    return __uint_as_float(b);
}

// ---------------- single fused prep ----------------
__global__ void prep_all(const float* __restrict__ aW1, const float* __restrict__ scW1,
                         const float* __restrict__ aW2, const float* __restrict__ scW2,
                         const float* __restrict__ ab1, const float* __restrict__ ab2,
                         const float* __restrict__ sb1, const float* __restrict__ sb2,
                         const float* __restrict__ sW3, const float* __restrict__ aW3)
{
    int tid = threadIdx.x;
    if (blockIdx.x == 0) {
        if (tid < 160) {
            bool ok = tid < 150;
            g_ba1[tid] = ok ? ab1[tid] : 0.f;
            g_ba2[tid] = ok ? ab2[tid] : 0.f;
            g_b1 [tid] = ok ? sb1[tid] : 0.f;
            g_b2 [tid] = ok ? sb2[tid] : 0.f;
            g_w3 [tid] = ok ? sW3[tid] : 0.f;
            g_wa3[tid] = ok ? aW3[tid] : 0.f;
        }
        if (tid == 0) { g_ctr = 0; g_maxbits = 0u; }
    }
    const int total = 114 * 2560;
    for (int idx = blockIdx.x * blockDim.x + tid; idx < total;
         idx += gridDim.x * blockDim.x) {
        int c   = idx / 2560;
        int rem = idx - c * 2560;
        int nn  = rem >> 4;
        int kk  = rem & 15;
        const float* W; int K; int lc;
        if      (c < 25)  { W = aW1;             K = 400; lc = c;       }
        else if (c < 50)  { W = scW1;            K = 400; lc = c - 25;  }
        else if (c < 75)  { W = scW1 + 400*150;  K = 400; lc = c - 50;  }
        else if (c < 94)  { W = scW1 + 800*150;  K = 300; lc = c - 75;  }
        else if (c < 104) { W = aW2;             K = 150; lc = c - 94;  }
        else              { W = scW2;            K = 150; lc = c - 104; }
        int k = lc * 16 + kk;
        float v = (k < K && nn < 150) ? W[k * 150 + nn] : 0.f;
        unsigned short h, l;
        split_bf16(v, h, l);
        unsigned short* dst = (unsigned short*)(g_Wimg + (size_t)c * CH_ELEMS + nn * 40);
        dst[kk]      = h;
        dst[16 + kk] = l;
        if (kk < 8) dst[32 + kk] = 0;
    }
}

// ---------------- staging helpers ----------------
__device__ __forceinline__ void stage_A(const float* __restrict__ X, int ldx,
                                        int Kreal, int m0, int M, int c,
                                        __nv_bfloat16* __restrict__ Abuf, int tid)
{
    int r  = tid >> 2;
    int kq = tid & 3;
    int m  = m0 + r;
    int k0 = c * 16 + kq * 4;
    float4 v = make_float4(0.f, 0.f, 0.f, 0.f);
    if (m < M) {
        if (k0 + 3 < Kreal) {
            v = *(const float4*)(X + (size_t)m * ldx + k0);
        } else {
            float* pv = (float*)&v;
            for (int j = 0; j < 4; j++)
                if (k0 + j < Kreal) pv[j] = X[(size_t)m * ldx + k0 + j];
        }
    }
    unsigned short h[4], l[4];
    split_bf16(v.x, h[0], l[0]); split_bf16(v.y, h[1], l[1]);
    split_bf16(v.z, h[2], l[2]); split_bf16(v.w, h[3], l[3]);
    unsigned short* dst = (unsigned short*)(Abuf + r * 40 + kq * 4);
    *(uint2*)dst        = make_uint2((unsigned)h[0] | ((unsigned)h[1] << 16),
                                     (unsigned)h[2] | ((unsigned)h[3] << 16));
    *(uint2*)(dst + 16) = make_uint2((unsigned)l[0] | ((unsigned)l[1] << 16),
                                     (unsigned)l[2] | ((unsigned)l[3] << 16));
}

__device__ __forceinline__ void stage_B(const __nv_bfloat16* __restrict__ img, int c,
                                        __nv_bfloat16* __restrict__ Bbuf, int tid)
{
    const float4* src = (const float4*)(img + (size_t)c * CH_ELEMS);
    float4* dst = (float4*)Bbuf;
    for (int i = tid; i < 800; i += 256) dst[i] = src[i];
}

// ---------------- core MMA tile macro (8-warp layout, 256 thr) ----------------
#define MMA_CHUNK(aBuf, bBuf)                                                   \
    {                                                                           \
        unsigned ah[4], al[4];                                                  \
        ldmx4(ah, (aBuf) + aOff);                                               \
        ldmx4(al, (aBuf) + aOff + 32);                                          \
        _Pragma("unroll")                                                       \
        for (int p = 0; p < 5; p++) {                                           \
            unsigned bh[4], bl[4];                                              \
            unsigned baddr = (bBuf) + (unsigned)((nw * 80 + p * 16) * 80) + bOff; \
            ldmx4(bh, baddr);                                                   \
            ldmx4(bl, baddr + 32);                                              \
            mma16816(acc[2 * p],     ah, bh);                                   \
            mma16816(acc[2 * p],     ah, bl);                                   \
            mma16816(acc[2 * p],     al, bh);                                   \
            mma16816(acc[2 * p + 1], ah, bh + 2);                               \
            mma16816(acc[2 * p + 1], ah, bl + 2);                               \
            mma16816(acc[2 * p + 1], al, bh + 2);                               \
        }                                                                       \
    }

// 16-warp layout: each warp 16 rows x 40 cols, B via ldmatrix.x2 per n8
#define MMA_CHUNK_W(aBuf, bBuf)                                                 \
    {                                                                           \
        unsigned ah[4], al[4];                                                  \
        ldmx4(ah, (aBuf) + aOff);                                               \
        ldmx4(al, (aBuf) + aOff + 32);                                          \
        _Pragma("unroll")                                                       \
        for (int p = 0; p < 5; p++) {                                           \
            unsigned bh[2], bl[2];                                              \
            unsigned baddr = (bBuf) + (unsigned)((nw * 40 + p * 8) * 80) + bOff2; \
            ldmx2(bh, baddr);                                                   \
            ldmx2(bl, baddr + 32);                                              \
            mma16816(acc[p], ah, bh);                                           \
            mma16816(acc[p], ah, bl);                                           \
            mma16816(acc[p], al, bh);                                           \
        }                                                                       \
    }

// ---------------- batched GEMM: 4 independent jobs via blockIdx.y ----------------
__global__ __launch_bounds__(256, 2) void gemmA(
    const float* __restrict__ states, const float* __restrict__ embeds,
    float* __restrict__ AH1, float* __restrict__ AP,
    float* __restrict__ BP,  float* __restrict__ PP)
{
    __shared__ __nv_bfloat16 As[2 * 64 * 40];
    __shared__ __nv_bfloat16 Bs[2 * 160 * 40];

    const float* X; int ldx, Kreal, chunks; const __nv_bfloat16* img;
    const float* biasPad; int dorelu; float* Y;
    switch (blockIdx.y) {
        case 0: X = states; ldx = 400; Kreal = 400; chunks = 25;
                img = g_Wimg + O_A1; biasPad = g_ba1; dorelu = 1; Y = AH1; break;
        case 1: X = states; ldx = 400; Kreal = 400; chunks = 25;
                img = g_Wimg + O_SA; biasPad = nullptr; dorelu = 0; Y = AP; break;
        case 2: X = states; ldx = 400; Kreal = 400; chunks = 25;
                img = g_Wimg + O_SB; biasPad = nullptr; dorelu = 0; Y = BP; break;
        default: X = embeds; ldx = 300; Kreal = 300; chunks = 19;
                img = g_Wimg + O_SP; biasPad = nullptr; dorelu = 0; Y = PP; break;
    }
    const int M = T_TOK;
    const int tid  = threadIdx.x;
    const int lane = tid & 31;
    const int warp = tid >> 5;
    const int mw   = warp & 3;
    const int nw   = warp >> 2;
    const int m0   = blockIdx.x * 64;

    float acc[10][4];
#pragma unroll
    for (int t = 0; t < 10; t++)
#pragma unroll
        for (int j = 0; j < 4; j++) acc[t][j] = 0.f;

    const int aRow = (lane & 7) + ((lane & 8) ? 8 : 0);
    const unsigned aOff = (unsigned)((mw * 16 + aRow) * 80 + ((lane & 16) ? 16 : 0));
    const int bRow = (lane & 7) + ((lane & 16) ? 8 : 0);
    const unsigned bOff = (unsigned)(bRow * 80 + ((lane & 8) ? 16 : 0));
    const unsigned asBase = cvta_s(As);
    const unsigned bsBase = cvta_s(Bs);

    stage_A(X, ldx, Kreal, m0, M, 0, As, tid);
    stage_B(img, 0, Bs, tid);
    __syncthreads();

    for (int c = 0; c < chunks; c++) {
        int cur = c & 1;
        if (c + 1 < chunks) {
            stage_A(X, ldx, Kreal, m0, M, c + 1, As + (cur ^ 1) * 2560, tid);
            stage_B(img, c + 1, Bs + (cur ^ 1) * 6400, tid);
        }
        unsigned aBuf = asBase + cur * 5120;
        unsigned bBuf = bsBase + cur * 12800;
        MMA_CHUNK(aBuf, bBuf);
        __syncthreads();
    }

    const int r1 = m0 + mw * 16 + (lane >> 2);
    const int cBase = nw * 80 + 2 * (lane & 3);
#pragma unroll
    for (int t = 0; t < 10; t++) {
        int col = cBase + t * 8;
        float b0 = 0.f, b1v = 0.f;
        if (biasPad) { b0 = biasPad[col]; b1v = biasPad[col + 1]; }
        float2 vA = make_float2(acc[t][0] + b0, acc[t][1] + b1v);
        float2 vB = make_float2(acc[t][2] + b0, acc[t][3] + b1v);
        if (dorelu) {
            vA.x = fmaxf(vA.x, 0.f); vA.y = fmaxf(vA.y, 0.f);
            vB.x = fmaxf(vB.x, 0.f); vB.y = fmaxf(vB.y, 0.f);
        }
        if (r1 < M)     *(float2*)(Y + (size_t)r1 * LDO + col)       = vA;
        if (r1 + 8 < M) *(float2*)(Y + (size_t)(r1 + 8) * LDO + col) = vB;
    }
}

// ---------------- attn layer2 + fused logits + global max ----------------
__global__ __launch_bounds__(256, 2) void attn2_k(
    const float* __restrict__ AH1, const float* __restrict__ ab3,
    float* __restrict__ LG)
{
    __shared__ __nv_bfloat16 As[2 * 64 * 40];
    __shared__ __nv_bfloat16 Bs[2 * 160 * 40];
    __shared__ float red2[128];
    __shared__ float bmax[2];

    const int tid  = threadIdx.x;
    const int lane = tid & 31;
    const int warp = tid >> 5;
    const int mw   = warp & 3;
    const int nw   = warp >> 2;
    const int m0   = blockIdx.x * 64;
    const int M    = T_TOK;
    const __nv_bfloat16* img = g_Wimg + O_A2;

    float acc[10][4];
#pragma unroll
    for (int t = 0; t < 10; t++)
#pragma unroll
        for (int j = 0; j < 4; j++) acc[t][j] = 0.f;

    const int aRow = (lane & 7) + ((lane & 8) ? 8 : 0);
    const unsigned aOff = (unsigned)((mw * 16 + aRow) * 80 + ((lane & 16) ? 16 : 0));
    const int bRow = (lane & 7) + ((lane & 16) ? 8 : 0);
    const unsigned bOff = (unsigned)(bRow * 80 + ((lane & 8) ? 16 : 0));
    const unsigned asBase = cvta_s(As);
    const unsigned bsBase = cvta_s(Bs);

    stage_A(AH1, LDO, 160, m0, M, 0, As, tid);
    stage_B(img, 0, Bs, tid);
    __syncthreads();

    for (int c = 0; c < 10; c++) {
        int cur = c & 1;
        if (c + 1 < 10) {
            stage_A(AH1, LDO, 160, m0, M, c + 1, As + (cur ^ 1) * 2560, tid);
            stage_B(img, c + 1, Bs + (cur ^ 1) * 6400, tid);
        }
        unsigned aBuf = asBase + cur * 5120;
        unsigned bBuf = bsBase + cur * 12800;
        MMA_CHUNK(aBuf, bBuf);
        __syncthreads();
    }

    const int cBase = nw * 80 + 2 * (lane & 3);
    float s1 = 0.f, s2 = 0.f;
#pragma unroll
    for (int t = 0; t < 10; t++) {
        int col = cBase + t * 8;
        float2 b2 = *(const float2*)(g_ba2 + col);
        float2 w3 = *(const float2*)(g_wa3 + col);
        s1 += fmaxf(acc[t][0] + b2.x, 0.f) * w3.x + fmaxf(acc[t][1] + b2.y, 0.f) * w3.y;
        s2 += fmaxf(acc[t][2] + b2.x, 0.f) * w3.x + fmaxf(acc[t][3] + b2.y, 0.f) * w3.y;
    }
    s1 += __shfl_xor_sync(0xffffffffu, s1, 1);
    s1 += __shfl_xor_sync(0xffffffffu, s1, 2);
    s2 += __shfl_xor_sync(0xffffffffu, s2, 1);
    s2 += __shfl_xor_sync(0xffffffffu, s2, 2);
    if ((lane & 3) == 0) {
        int row = mw * 16 + (lane >> 2);
        red2[row * 2 + nw]       = s1;
        red2[(row + 8) * 2 + nw] = s2;
    }
    __syncthreads();
    if (tid < 64) {
        int m = m0 + tid;
        float v = red2[tid * 2] + red2[tid * 2 + 1] + ab3[0];
        float mv = -3.4e38f;
        if (m < M) { LG[m] = v; mv = v; }
#pragma unroll
        for (int o = 16; o; o >>= 1) mv = fmaxf(mv, __shfl_xor_sync(0xffffffffu, mv, o));
        if ((tid & 31) == 0) bmax[tid >> 5] = mv;
    }
    __syncthreads();
    if (tid == 0) atomicMax(&g_maxbits, encf(fmaxf(bmax[0], bmax[1])));
}

// ---------------- persistent span kernel: 512 threads, 16-warp MMA ----------------
// smem: W2s 128000 @0, H1s 51200 @128000, NS 40960 @179200, eg 320 @220160,
//       sD 256 @220480, invD 256 @220736, red 1024 @220992 -> 222016
#define SPAN_SMEM 222016
#define N_UNITS (313 * 3)

__global__ __launch_bounds__(512, 1) void span_k(
    const float* __restrict__ AP, const float* __restrict__ BP,
    const float* __restrict__ PP, const float* __restrict__ LG,
    const float* __restrict__ b3, float* __restrict__ out)
{
    extern __shared__ char sm[];
    __nv_bfloat16* W2s = (__nv_bfloat16*)sm;
    __nv_bfloat16* H1s = (__nv_bfloat16*)(sm + 128000);
    float* NS   = (float*)(sm + 179200);
    float* eg   = (float*)(sm + 220160);
    float* sD   = (float*)(sm + 220480);
    float* invD = (float*)(sm + 220736);
    float* red  = (float*)(sm + 220992);
    __shared__ int s_u;

    const int tid  = threadIdx.x;
    const int lane = tid & 31;
    const int warp = tid >> 5;
    const int mw   = warp & 3;   // 16-row group
    const int nw   = warp >> 2;  // 40-col group (0..3)

    const int aRow = (lane & 7) + ((lane & 8) ? 8 : 0);
    const unsigned aOff = (unsigned)((mw * 16 + aRow) * 80 + ((lane & 16) ? 16 : 0));
    const unsigned bOff2 = (unsigned)((lane & 7) * 80 + ((lane & 8) ? 16 : 0));
    const unsigned h1Base = cvta_s(H1s);
    const unsigned w2Base = cvta_s(W2s);

    // load full W2 image (128 KB) once
    {
        const float4* src = (const float4*)(g_Wimg + O_W2);
        float4* dst = (float4*)W2s;
        for (int i = tid; i < 8000; i += 512) dst[i] = src[i];
    }

    const float Mx = decf(g_maxbits);

    while (true) {
        if (tid == 0) s_u = atomicAdd(&g_ctr, 1);
        __syncthreads();
        int u = s_u;
        if (u >= N_UNITS) break;
        int tile = u / 3;
        int grp  = u - tile * 3;
        int s0 = tile * 64;
        int n0   = (grp == 0) ? 1 : (grp == 1 ? 5 : 8);
        int nend = (grp == 0) ? 5 : (grp == 1 ? 8 : 11);

        if (tid < 80) {
            int t = s0 + tid;
            eg[tid] = (t < T_TOK) ? __expf(LG[t] - Mx) : 0.f;
        }
        __syncthreads();

        // init NS (numerator for width n0) and sD/invD
#pragma unroll
        for (int it = 0; it < 5; it++) {
            int idx = tid + it * 512;
            int i = idx / 40, g = idx - i * 40, c0 = g * 4;
            float4 a = make_float4(0.f, 0.f, 0.f, 0.f);
            for (int j = 0; j < n0; j++) {
                float e = eg[i + j];
                float4 p = *(const float4*)(PP + (size_t)(s0 + i + j) * LDO + c0);
                a.x += e * p.x; a.y += e * p.y;
                a.z += e * p.z; a.w += e * p.w;
            }
            *(float4*)(NS + i * 160 + c0) = a;
        }
        if (tid < 64) {
            float d = 0.f;
            for (int j = 0; j < n0; j++) d += eg[tid + j];
            sD[tid] = d;
            invD[tid] = 1.f / d;
        }
        __syncthreads();

        for (int n = n0; n < nend; n++) {
            const int S = T_TOK - n + 1;

            // build H1 = relu(AP[s] + BP[s+n-1] + b1 + NS*invD) -> hi/lo split
#pragma unroll
            for (int it = 0; it < 5; it++) {
                int idx = tid + it * 512;
                int i = idx / 40, g = idx - i * 40, c0 = g * 4;
                int s = s0 + i;
                float4 v = make_float4(0.f, 0.f, 0.f, 0.f);
                if (s < S) {
                    float4 a4 = *(const float4*)(AP + (size_t)s * LDO + c0);
                    float4 q4 = *(const float4*)(BP + (size_t)(s + n - 1) * LDO + c0);
                    float4 b4 = *(const float4*)(g_b1 + c0);
                    float4 ns = *(const float4*)(NS + i * 160 + c0);
                    float id = invD[i];
                    v.x = fmaxf(a4.x + q4.x + b4.x + ns.x * id, 0.f);
                    v.y = fmaxf(a4.y + q4.y + b4.y + ns.y * id, 0.f);
                    v.z = fmaxf(a4.z + q4.z + b4.z + ns.z * id, 0.f);
                    v.w = fmaxf(a4.w + q4.w + b4.w + ns.w * id, 0.f);
                }
                unsigned short h[4], l[4];
                split_bf16(v.x, h[0], l[0]); split_bf16(v.y, h[1], l[1]);
                split_bf16(v.z, h[2], l[2]); split_bf16(v.w, h[3], l[3]);
                int cch = g >> 2, kk = (g & 3) * 4;
                unsigned short* dst = (unsigned short*)(H1s + (size_t)(cch * 64 + i) * 40 + kk);
                *(uint2*)dst        = make_uint2((unsigned)h[0] | ((unsigned)h[1] << 16),
                                                 (unsigned)h[2] | ((unsigned)h[3] << 16));
                *(uint2*)(dst + 16) = make_uint2((unsigned)l[0] | ((unsigned)l[1] << 16),
                                                 (unsigned)l[2] | ((unsigned)l[3] << 16));
            }
            __syncthreads();

            // MMA: W2 and H1 resident, 16-warp split
            float acc[5][4];
#pragma unroll
            for (int t = 0; t < 5; t++)
#pragma unroll
                for (int j = 0; j < 4; j++) acc[t][j] = 0.f;
#pragma unroll
            for (int c = 0; c < 10; c++) {
                unsigned aBuf = h1Base + (unsigned)(c * 5120);
                unsigned bBuf = w2Base + (unsigned)(c * 12800);
                MMA_CHUNK_W(aBuf, bBuf);
            }

            // epilogue: relu(H2 + b2) . w3, reduce
            const int cBase = nw * 40 + 2 * (lane & 3);
            float s1 = 0.f, s2 = 0.f;
#pragma unroll
            for (int p = 0; p < 5; p++) {
                int col = cBase + p * 8;
                float2 w3 = *(const float2*)(g_w3 + col);
                float2 b2 = *(const float2*)(g_b2 + col);
                s1 += fmaxf(acc[p][0] + b2.x, 0.f) * w3.x + fmaxf(acc[p][1] + b2.y, 0.f) * w3.y;
                s2 += fmaxf(acc[p][2] + b2.x, 0.f) * w3.x + fmaxf(acc[p][3] + b2.y, 0.f) * w3.y;
            }
            s1 += __shfl_xor_sync(0xffffffffu, s1, 1);
            s1 += __shfl_xor_sync(0xffffffffu, s1, 2);
            s2 += __shfl_xor_sync(0xffffffffu, s2, 1);
            s2 += __shfl_xor_sync(0xffffffffu, s2, 2);
            if ((lane & 3) == 0) {
                int row = mw * 16 + (lane >> 2);
                red[row * 4 + nw]       = s1;
                red[(row + 8) * 4 + nw] = s2;
            }
            __syncthreads();

            if (tid < 64) {
                int s = s0 + tid;
                if (s < S) {
                    long long off = (long long)(n - 1) * (T_TOK + 1)
                                  - (long long)(n - 1) * n / 2;
                    out[off + s] = red[tid * 4] + red[tid * 4 + 1]
                                 + red[tid * 4 + 2] + red[tid * 4 + 3] + b3[0];
                }
            }

            // incremental update for next width
            if (n + 1 < nend) {
#pragma unroll
                for (int it = 0; it < 5; it++) {
                    int idx = tid + it * 512;
                    int i = idx / 40, g = idx - i * 40, c0 = g * 4;
                    float e = eg[i + n];
                    float4 p = *(const float4*)(PP + (size_t)(s0 + i + n) * LDO + c0);
                    float4 ns = *(const float4*)(NS + i * 160 + c0);
                    ns.x += e * p.x; ns.y += e * p.y;
                    ns.z += e * p.z; ns.w += e * p.w;
                    *(float4*)(NS + i * 160 + c0) = ns;
                }
                if (tid < 64) {
                    sD[tid] += eg[tid + n];
                    invD[tid] = 1.f / sD[tid];
                }
            }
            __syncthreads();
        }
    }
}

// ---------------- host ----------------
extern "C" void kernel_launch(void* const* d_in, const int* in_sizes, int n_in,
                              void* d_out, int out_size)
{
    const float* embeds  = (const float*)d_in[0];
    const float* states  = (const float*)d_in[1];
    const float* attn_W1 = (const float*)d_in[2];
    const float* attn_b1 = (const float*)d_in[3];
    const float* attn_W2 = (const float*)d_in[4];
    const float* attn_b2 = (const float*)d_in[5];
    const float* attn_W3 = (const float*)d_in[6];
    const float* attn_b3 = (const float*)d_in[7];
    const float* sc_W1   = (const float*)d_in[8];
    const float* sc_b1   = (const float*)d_in[9];
    const float* sc_W2   = (const float*)d_in[10];
    const float* sc_b2   = (const float*)d_in[11];
    const float* sc_W3   = (const float*)d_in[12];
    const float* sc_b3   = (const float*)d_in[13];
    float* out = (float*)d_out;

    float *AH1, *AP, *BP, *PP, *LG;
    cudaGetSymbolAddress((void**)&AH1, g_AH1);
    cudaGetSymbolAddress((void**)&AP,  g_AP);
    cudaGetSymbolAddress((void**)&BP,  g_BP);
    cudaGetSymbolAddress((void**)&PP,  g_PP);
    cudaGetSymbolAddress((void**)&LG,  g_LG);

    const int gm = (T_TOK + 63) / 64;  // 313

    prep_all<<<148, 256>>>(attn_W1, sc_W1, attn_W2, sc_W2,
                           attn_b1, attn_b2, sc_b1, sc_b2, sc_W3, attn_W3);

    gemmA<<<dim3(gm, 4), 256>>>(states, embeds, AH1, AP, BP, PP);

    attn2_k<<<gm, 256>>>(AH1, attn_b3, LG);

    cudaFuncSetAttribute(span_k, cudaFuncAttributeMaxDynamicSharedMemorySize, SPAN_SMEM);
    span_k<<<148, 512, SPAN_SMEM>>>(AP, BP, PP, LG, sc_b3, out);
}

// round 9
// speedup vs baseline: 3.4049x; 1.0937x over previous
#include <cuda_runtime.h>
#include <cuda_bf16.h>

#define T_TOK 20000
#define LDO   160

// ---------------- scratch ----------------
__device__ __align__(256) float g_AH1[T_TOK * LDO];
__device__ __align__(256) float g_AP [T_TOK * LDO];
__device__ __align__(256) float g_BP [T_TOK * LDO];
__device__ __align__(256) float g_PP [(T_TOK + 64) * LDO];  // 64 zero pad rows
__device__ __align__(256) float g_LG [T_TOK];
__device__ int g_ctr;
__device__ unsigned g_maxbits;

// weight images: per k16-chunk: 160 rows(n) x 40 bf16 (16 hi | 16 lo | 8 pad)
#define CH_ELEMS 6400
#define O_A1 0
#define O_SA (25 * CH_ELEMS)
#define O_SB (50 * CH_ELEMS)
#define O_SP (75 * CH_ELEMS)
#define O_A2 (94 * CH_ELEMS)
#define O_W2 (104 * CH_ELEMS)
__device__ __align__(256) __nv_bfloat16 g_Wimg[114 * CH_ELEMS];

__device__ __align__(256) float g_ba1[160];
__device__ __align__(256) float g_ba2[160];
__device__ __align__(256) float g_b1 [160];
__device__ __align__(256) float g_b2 [160];
__device__ __align__(256) float g_w3 [160];
__device__ __align__(256) float g_wa3[160];

// ---------------- helpers ----------------
__device__ __forceinline__ unsigned cvta_s(const void* p) {
    return (unsigned)__cvta_generic_to_shared(p);
}
__device__ __forceinline__ void ldmx4(unsigned* r, unsigned addr) {
    asm volatile("ldmatrix.sync.aligned.m8n8.x4.shared.b16 {%0,%1,%2,%3}, [%4];"
        : "=r"(r[0]), "=r"(r[1]), "=r"(r[2]), "=r"(r[3]) : "r"(addr));
}
__device__ __forceinline__ void mma16816(float* d, const unsigned* a, const unsigned* b) {
    asm volatile(
        "mma.sync.aligned.m16n8k16.row.col.f32.bf16.bf16.f32 "
        "{%0,%1,%2,%3}, {%4,%5,%6,%7}, {%8,%9}, {%0,%1,%2,%3};"
        : "+f"(d[0]), "+f"(d[1]), "+f"(d[2]), "+f"(d[3])
        : "r"(a[0]), "r"(a[1]), "r"(a[2]), "r"(a[3]), "r"(b[0]), "r"(b[1]));
}
__device__ __forceinline__ void split_bf16(float v, unsigned short& h, unsigned short& l) {
    __nv_bfloat16 hb = __float2bfloat16_rn(v);
    __nv_bfloat16 lb = __float2bfloat16_rn(v - __bfloat162float(hb));
    h = __bfloat16_as_ushort(hb);
    l = __bfloat16_as_ushort(lb);
}
__device__ __forceinline__ unsigned encf(float x) {
    unsigned u = __float_as_uint(x);
    return (u & 0x80000000u) ? ~u : (u | 0x80000000u);
}
__device__ __forceinline__ float decf(unsigned u) {
    unsigned b = (u & 0x80000000u) ? (u & 0x7fffffffu) : ~u;
    return __uint_as_float(b);
}

// ---------------- single fused prep ----------------
__global__ void prep_all(const float* __restrict__ aW1, const float* __restrict__ scW1,
                         const float* __restrict__ aW2, const float* __restrict__ scW2,
                         const float* __restrict__ ab1, const float* __restrict__ ab2,
                         const float* __restrict__ sb1, const float* __restrict__ sb2,
                         const float* __restrict__ sW3, const float* __restrict__ aW3)
{
    int tid = threadIdx.x;
    if (blockIdx.x == 0) {
        if (tid < 160) {
            bool ok = tid < 150;
            g_ba1[tid] = ok ? ab1[tid] : 0.f;
            g_ba2[tid] = ok ? ab2[tid] : 0.f;
            g_b1 [tid] = ok ? sb1[tid] : 0.f;
            g_b2 [tid] = ok ? sb2[tid] : 0.f;
            g_w3 [tid] = ok ? sW3[tid] : 0.f;
            g_wa3[tid] = ok ? aW3[tid] : 0.f;
        }
        if (tid == 0) { g_ctr = 0; g_maxbits = 0u; }
    }
    const int total = 114 * 2560;
    for (int idx = blockIdx.x * blockDim.x + tid; idx < total;
         idx += gridDim.x * blockDim.x) {
        int c   = idx / 2560;
        int rem = idx - c * 2560;
        int nn  = rem >> 4;
        int kk  = rem & 15;
        const float* W; int K; int lc;
        if      (c < 25)  { W = aW1;             K = 400; lc = c;       }
        else if (c < 50)  { W = scW1;            K = 400; lc = c - 25;  }
        else if (c < 75)  { W = scW1 + 400*150;  K = 400; lc = c - 50;  }
        else if (c < 94)  { W = scW1 + 800*150;  K = 300; lc = c - 75;  }
        else if (c < 104) { W = aW2;             K = 150; lc = c - 94;  }
        else              { W = scW2;            K = 150; lc = c - 104; }
        int k = lc * 16 + kk;
        float v = (k < K && nn < 150) ? W[k * 150 + nn] : 0.f;
        unsigned short h, l;
        split_bf16(v, h, l);
        unsigned short* dst = (unsigned short*)(g_Wimg + (size_t)c * CH_ELEMS + nn * 40);
        dst[kk]      = h;
        dst[16 + kk] = l;
        if (kk < 8) dst[32 + kk] = 0;
    }
}

// ---------------- staging (512 threads, 128-row tiles) ----------------
__device__ __forceinline__ void stage_A128(const float* __restrict__ X, int ldx,
                                           int Kreal, int m0, int M, int c,
                                           __nv_bfloat16* __restrict__ Abuf, int tid)
{
    int r  = tid >> 2;        // 0..127
    int kq = tid & 3;
    int m  = m0 + r;
    int k0 = c * 16 + kq * 4;
    float4 v = make_float4(0.f, 0.f, 0.f, 0.f);
    if (m < M) {
        if (k0 + 3 < Kreal) {
            v = *(const float4*)(X + (size_t)m * ldx + k0);
        } else {
            float* pv = (float*)&v;
            for (int j = 0; j < 4; j++)
                if (k0 + j < Kreal) pv[j] = X[(size_t)m * ldx + k0 + j];
        }
    }
    unsigned short h[4], l[4];
    split_bf16(v.x, h[0], l[0]); split_bf16(v.y, h[1], l[1]);
    split_bf16(v.z, h[2], l[2]); split_bf16(v.w, h[3], l[3]);
    unsigned short* dst = (unsigned short*)(Abuf + r * 40 + kq * 4);
    *(uint2*)dst        = make_uint2((unsigned)h[0] | ((unsigned)h[1] << 16),
                                     (unsigned)h[2] | ((unsigned)h[3] << 16));
    *(uint2*)(dst + 16) = make_uint2((unsigned)l[0] | ((unsigned)l[1] << 16),
                                     (unsigned)l[2] | ((unsigned)l[3] << 16));
}

__device__ __forceinline__ void stage_B512(const __nv_bfloat16* __restrict__ img, int c,
                                           __nv_bfloat16* __restrict__ Bbuf, int tid)
{
    const float4* src = (const float4*)(img + (size_t)c * CH_ELEMS);
    float4* dst = (float4*)Bbuf;
    for (int i = tid; i < 800; i += 512) dst[i] = src[i];
}

// ---------------- core MMA macro (16 rows x 80 cols per warp) ----------------
#define MMA_CHUNK(aBuf, bBuf)                                                   \
    {                                                                           \
        unsigned ah[4], al[4];                                                  \
        ldmx4(ah, (aBuf) + aOff);                                               \
        ldmx4(al, (aBuf) + aOff + 32);                                          \
        _Pragma("unroll")                                                       \
        for (int p = 0; p < 5; p++) {                                           \
            unsigned bh[4], bl[4];                                              \
            unsigned baddr = (bBuf) + (unsigned)((nw * 80 + p * 16) * 80) + bOff; \
            ldmx4(bh, baddr);                                                   \
            ldmx4(bl, baddr + 32);                                              \
            mma16816(acc[2 * p],     ah, bh);                                   \
            mma16816(acc[2 * p],     ah, bl);                                   \
            mma16816(acc[2 * p],     al, bh);                                   \
            mma16816(acc[2 * p + 1], ah, bh + 2);                               \
            mma16816(acc[2 * p + 1], ah, bl + 2);                               \
            mma16816(acc[2 * p + 1], al, bh + 2);                               \
        }                                                                       \
    }

// span 16-warp layout: 16 rows x 40 cols, hi+lo B fused in one ldmatrix.x4
#define MMA_CHUNK_W(aBuf, bBuf)                                                 \
    {                                                                           \
        unsigned ah[4], al[4];                                                  \
        ldmx4(ah, (aBuf) + aOff);                                               \
        ldmx4(al, (aBuf) + aOff + 32);                                          \
        _Pragma("unroll")                                                       \
        for (int p = 0; p < 5; p++) {                                           \
            unsigned bb[4];                                                     \
            unsigned baddr = (bBuf) + (unsigned)((nw * 40 + p * 8) * 80) + bOff4; \
            ldmx4(bb, baddr);                                                   \
            mma16816(acc[p], ah, bb);                                           \
            mma16816(acc[p], ah, bb + 2);                                       \
            mma16816(acc[p], al, bb);                                           \
        }                                                                       \
    }

// ---------------- batched GEMM: 4 jobs, 128-row tiles, 512 threads ----------------
__global__ __launch_bounds__(512, 1) void gemmA(
    const float* __restrict__ states, const float* __restrict__ embeds,
    float* __restrict__ AH1, float* __restrict__ AP,
    float* __restrict__ BP,  float* __restrict__ PP)
{
    __shared__ __nv_bfloat16 As[2 * 128 * 40];
    __shared__ __nv_bfloat16 Bs[2 * 160 * 40];

    const float* X; int ldx, Kreal, chunks; const __nv_bfloat16* img;
    const float* biasPad; int dorelu; float* Y;
    switch (blockIdx.y) {
        case 0: X = states; ldx = 400; Kreal = 400; chunks = 25;
                img = g_Wimg + O_A1; biasPad = g_ba1; dorelu = 1; Y = AH1; break;
        case 1: X = states; ldx = 400; Kreal = 400; chunks = 25;
                img = g_Wimg + O_SA; biasPad = nullptr; dorelu = 0; Y = AP; break;
        case 2: X = states; ldx = 400; Kreal = 400; chunks = 25;
                img = g_Wimg + O_SB; biasPad = nullptr; dorelu = 0; Y = BP; break;
        default: X = embeds; ldx = 300; Kreal = 300; chunks = 19;
                img = g_Wimg + O_SP; biasPad = nullptr; dorelu = 0; Y = PP; break;
    }
    const int M = T_TOK;
    const int tid  = threadIdx.x;
    const int lane = tid & 31;
    const int warp = tid >> 5;
    const int mw   = warp & 7;   // 8 groups of 16 rows = 128
    const int nw   = warp >> 3;  // 2 groups of 80 cols
    const int m0   = blockIdx.x * 128;

    float acc[10][4];
#pragma unroll
    for (int t = 0; t < 10; t++)
#pragma unroll
        for (int j = 0; j < 4; j++) acc[t][j] = 0.f;

    const int aRow = (lane & 7) + ((lane & 8) ? 8 : 0);
    const unsigned aOff = (unsigned)((mw * 16 + aRow) * 80 + ((lane & 16) ? 16 : 0));
    const int bRow = (lane & 7) + ((lane & 16) ? 8 : 0);
    const unsigned bOff = (unsigned)(bRow * 80 + ((lane & 8) ? 16 : 0));
    const unsigned asBase = cvta_s(As);
    const unsigned bsBase = cvta_s(Bs);

    stage_A128(X, ldx, Kreal, m0, M, 0, As, tid);
    stage_B512(img, 0, Bs, tid);
    __syncthreads();

    for (int c = 0; c < chunks; c++) {
        int cur = c & 1;
        if (c + 1 < chunks) {
            stage_A128(X, ldx, Kreal, m0, M, c + 1, As + (cur ^ 1) * 5120, tid);
            stage_B512(img, c + 1, Bs + (cur ^ 1) * 6400, tid);
        }
        unsigned aBuf = asBase + cur * 10240;
        unsigned bBuf = bsBase + cur * 12800;
        MMA_CHUNK(aBuf, bBuf);
        __syncthreads();
    }

    const int r1 = m0 + mw * 16 + (lane >> 2);
    const int cBase = nw * 80 + 2 * (lane & 3);
#pragma unroll
    for (int t = 0; t < 10; t++) {
        int col = cBase + t * 8;
        float b0 = 0.f, b1v = 0.f;
        if (biasPad) { b0 = biasPad[col]; b1v = biasPad[col + 1]; }
        float2 vA = make_float2(acc[t][0] + b0, acc[t][1] + b1v);
        float2 vB = make_float2(acc[t][2] + b0, acc[t][3] + b1v);
        if (dorelu) {
            vA.x = fmaxf(vA.x, 0.f); vA.y = fmaxf(vA.y, 0.f);
            vB.x = fmaxf(vB.x, 0.f); vB.y = fmaxf(vB.y, 0.f);
        }
        if (r1 < M)     *(float2*)(Y + (size_t)r1 * LDO + col)       = vA;
        if (r1 + 8 < M) *(float2*)(Y + (size_t)(r1 + 8) * LDO + col) = vB;
    }
}

// ---------------- attn layer2 + fused logits + global max (128-row tiles) ----------------
__global__ __launch_bounds__(512, 1) void attn2_k(
    const float* __restrict__ AH1, const float* __restrict__ ab3,
    float* __restrict__ LG)
{
    __shared__ __nv_bfloat16 As[2 * 128 * 40];
    __shared__ __nv_bfloat16 Bs[2 * 160 * 40];
    __shared__ float red2[256];
    __shared__ float bmax[4];

    const int tid  = threadIdx.x;
    const int lane = tid & 31;
    const int warp = tid >> 5;
    const int mw   = warp & 7;
    const int nw   = warp >> 3;
    const int m0   = blockIdx.x * 128;
    const int M    = T_TOK;
    const __nv_bfloat16* img = g_Wimg + O_A2;

    float acc[10][4];
#pragma unroll
    for (int t = 0; t < 10; t++)
#pragma unroll
        for (int j = 0; j < 4; j++) acc[t][j] = 0.f;

    const int aRow = (lane & 7) + ((lane & 8) ? 8 : 0);
    const unsigned aOff = (unsigned)((mw * 16 + aRow) * 80 + ((lane & 16) ? 16 : 0));
    const int bRow = (lane & 7) + ((lane & 16) ? 8 : 0);
    const unsigned bOff = (unsigned)(bRow * 80 + ((lane & 8) ? 16 : 0));
    const unsigned asBase = cvta_s(As);
    const unsigned bsBase = cvta_s(Bs);

    stage_A128(AH1, LDO, 160, m0, M, 0, As, tid);
    stage_B512(img, 0, Bs, tid);
    __syncthreads();

    for (int c = 0; c < 10; c++) {
        int cur = c & 1;
        if (c + 1 < 10) {
            stage_A128(AH1, LDO, 160, m0, M, c + 1, As + (cur ^ 1) * 5120, tid);
            stage_B512(img, c + 1, Bs + (cur ^ 1) * 6400, tid);
        }
        unsigned aBuf = asBase + cur * 10240;
        unsigned bBuf = bsBase + cur * 12800;
        MMA_CHUNK(aBuf, bBuf);
        __syncthreads();
    }

    // fused: logits = relu(H2 + ba2) . wa3
    const int cBase = nw * 80 + 2 * (lane & 3);
    float s1 = 0.f, s2 = 0.f;
#pragma unroll
    for (int t = 0; t < 10; t++) {
        int col = cBase + t * 8;
        float2 b2 = *(const float2*)(g_ba2 + col);
        float2 w3 = *(const float2*)(g_wa3 + col);
        s1 += fmaxf(acc[t][0] + b2.x, 0.f) * w3.x + fmaxf(acc[t][1] + b2.y, 0.f) * w3.y;
        s2 += fmaxf(acc[t][2] + b2.x, 0.f) * w3.x + fmaxf(acc[t][3] + b2.y, 0.f) * w3.y;
    }
    s1 += __shfl_xor_sync(0xffffffffu, s1, 1);
    s1 += __shfl_xor_sync(0xffffffffu, s1, 2);
    s2 += __shfl_xor_sync(0xffffffffu, s2, 1);
    s2 += __shfl_xor_sync(0xffffffffu, s2, 2);
    if ((lane & 3) == 0) {
        int row = mw * 16 + (lane >> 2);
        red2[row * 2 + nw]       = s1;
        red2[(row + 8) * 2 + nw] = s2;
    }
    __syncthreads();
    if (tid < 128) {
        int m = m0 + tid;
        float v = red2[tid * 2] + red2[tid * 2 + 1] + ab3[0];
        float mv = -3.4e38f;
        if (m < M) { LG[m] = v; mv = v; }
#pragma unroll
        for (int o = 16; o; o >>= 1) mv = fmaxf(mv, __shfl_xor_sync(0xffffffffu, mv, o));
        if ((tid & 31) == 0) bmax[tid >> 5] = mv;
    }
    __syncthreads();
    if (tid == 0)
        atomicMax(&g_maxbits, encf(fmaxf(fmaxf(bmax[0], bmax[1]),
                                         fmaxf(bmax[2], bmax[3]))));
}

// ---------------- persistent span kernel: 512 threads, fused B ldmatrix ----------------
// smem: W2s 128000 @0, H1s 51200 @128000, NS 40960 @179200, eg 320 @220160,
//       sD 256 @220480, invD 256 @220736, red 1024 @220992 -> 222016
#define SPAN_SMEM 222016
#define N_UNITS (313 * 3)

__global__ __launch_bounds__(512, 1) void span_k(
    const float* __restrict__ AP, const float* __restrict__ BP,
    const float* __restrict__ PP, const float* __restrict__ LG,
    const float* __restrict__ b3, float* __restrict__ out)
{
    extern __shared__ char sm[];
    __nv_bfloat16* W2s = (__nv_bfloat16*)sm;
    __nv_bfloat16* H1s = (__nv_bfloat16*)(sm + 128000);
    float* NS   = (float*)(sm + 179200);
    float* eg   = (float*)(sm + 220160);
    float* sD   = (float*)(sm + 220480);
    float* invD = (float*)(sm + 220736);
    float* red  = (float*)(sm + 220992);
    __shared__ int s_u;

    const int tid  = threadIdx.x;
    const int lane = tid & 31;
    const int warp = tid >> 5;
    const int mw   = warp & 3;   // 16-row group
    const int nw   = warp >> 2;  // 40-col group (0..3)

    const int aRow = (lane & 7) + ((lane & 8) ? 8 : 0);
    const unsigned aOff = (unsigned)((mw * 16 + aRow) * 80 + ((lane & 16) ? 16 : 0));
    const unsigned bOff4 = (unsigned)((lane & 7) * 80 + (((lane >> 3) & 3) * 16));
    const unsigned h1Base = cvta_s(H1s);
    const unsigned w2Base = cvta_s(W2s);

    // load full W2 image (128 KB) once
    {
        const float4* src = (const float4*)(g_Wimg + O_W2);
        float4* dst = (float4*)W2s;
        for (int i = tid; i < 8000; i += 512) dst[i] = src[i];
    }

    const float Mx = decf(g_maxbits);

    while (true) {
        if (tid == 0) s_u = atomicAdd(&g_ctr, 1);
        __syncthreads();
        int u = s_u;
        if (u >= N_UNITS) break;
        int tile = u / 3;
        int grp  = u - tile * 3;
        int s0 = tile * 64;
        int n0   = (grp == 0) ? 1 : (grp == 1 ? 5 : 8);
        int nend = (grp == 0) ? 5 : (grp == 1 ? 8 : 11);

        if (tid < 80) {
            int t = s0 + tid;
            eg[tid] = (t < T_TOK) ? __expf(LG[t] - Mx) : 0.f;
        }
        __syncthreads();

        // init NS (numerator for width n0) and sD/invD
#pragma unroll
        for (int it = 0; it < 5; it++) {
            int idx = tid + it * 512;
            int i = idx / 40, g = idx - i * 40, c0 = g * 4;
            float4 a = make_float4(0.f, 0.f, 0.f, 0.f);
            for (int j = 0; j < n0; j++) {
                float e = eg[i + j];
                float4 p = *(const float4*)(PP + (size_t)(s0 + i + j) * LDO + c0);
                a.x += e * p.x; a.y += e * p.y;
                a.z += e * p.z; a.w += e * p.w;
            }
            *(float4*)(NS + i * 160 + c0) = a;
        }
        if (tid < 64) {
            float d = 0.f;
            for (int j = 0; j < n0; j++) d += eg[tid + j];
            sD[tid] = d;
            invD[tid] = 1.f / d;
        }
        __syncthreads();

        for (int n = n0; n < nend; n++) {
            const int S = T_TOK - n + 1;

            // build H1 = relu(AP[s] + BP[s+n-1] + b1 + NS*invD) -> hi/lo split
#pragma unroll
            for (int it = 0; it < 5; it++) {
                int idx = tid + it * 512;
                int i = idx / 40, g = idx - i * 40, c0 = g * 4;
                int s = s0 + i;
                float4 v = make_float4(0.f, 0.f, 0.f, 0.f);
                if (s < S) {
                    float4 a4 = *(const float4*)(AP + (size_t)s * LDO + c0);
                    float4 q4 = *(const float4*)(BP + (size_t)(s + n - 1) * LDO + c0);
                    float4 b4 = *(const float4*)(g_b1 + c0);
                    float4 ns = *(const float4*)(NS + i * 160 + c0);
                    float id = invD[i];
                    v.x = fmaxf(a4.x + q4.x + b4.x + ns.x * id, 0.f);
                    v.y = fmaxf(a4.y + q4.y + b4.y + ns.y * id, 0.f);
                    v.z = fmaxf(a4.z + q4.z + b4.z + ns.z * id, 0.f);
                    v.w = fmaxf(a4.w + q4.w + b4.w + ns.w * id, 0.f);
                }
                unsigned short h[4], l[4];
                split_bf16(v.x, h[0], l[0]); split_bf16(v.y, h[1], l[1]);
                split_bf16(v.z, h[2], l[2]); split_bf16(v.w, h[3], l[3]);
                int cch = g >> 2, kk = (g & 3) * 4;
                unsigned short* dst = (unsigned short*)(H1s + (size_t)(cch * 64 + i) * 40 + kk);
                *(uint2*)dst        = make_uint2((unsigned)h[0] | ((unsigned)h[1] << 16),
                                                 (unsigned)h[2] | ((unsigned)h[3] << 16));
                *(uint2*)(dst + 16) = make_uint2((unsigned)l[0] | ((unsigned)l[1] << 16),
                                                 (unsigned)l[2] | ((unsigned)l[3] << 16));
            }
            __syncthreads();

            // MMA: W2 and H1 resident, 16-warp split, fused hi/lo B loads
            float acc[5][4];
#pragma unroll
            for (int t = 0; t < 5; t++)
#pragma unroll
                for (int j = 0; j < 4; j++) acc[t][j] = 0.f;
#pragma unroll
            for (int c = 0; c < 10; c++) {
                unsigned aBuf = h1Base + (unsigned)(c * 5120);
                unsigned bBuf = w2Base + (unsigned)(c * 12800);
                MMA_CHUNK_W(aBuf, bBuf);
            }

            // epilogue: relu(H2 + b2) . w3, reduce
            const int cBase = nw * 40 + 2 * (lane & 3);
            float s1 = 0.f, s2 = 0.f;
#pragma unroll
            for (int p = 0; p < 5; p++) {
                int col = cBase + p * 8;
                float2 w3 = *(const float2*)(g_w3 + col);
                float2 b2 = *(const float2*)(g_b2 + col);
                s1 += fmaxf(acc[p][0] + b2.x, 0.f) * w3.x + fmaxf(acc[p][1] + b2.y, 0.f) * w3.y;
                s2 += fmaxf(acc[p][2] + b2.x, 0.f) * w3.x + fmaxf(acc[p][3] + b2.y, 0.f) * w3.y;
            }
            s1 += __shfl_xor_sync(0xffffffffu, s1, 1);
            s1 += __shfl_xor_sync(0xffffffffu, s1, 2);
            s2 += __shfl_xor_sync(0xffffffffu, s2, 1);
            s2 += __shfl_xor_sync(0xffffffffu, s2, 2);
            if ((lane & 3) == 0) {
                int row = mw * 16 + (lane >> 2);
                red[row * 4 + nw]       = s1;
                red[(row + 8) * 4 + nw] = s2;
            }
            __syncthreads();

            if (tid < 64) {
                int s = s0 + tid;
                if (s < S) {
                    long long off = (long long)(n - 1) * (T_TOK + 1)
                                  - (long long)(n - 1) * n / 2;
                    out[off + s] = red[tid * 4] + red[tid * 4 + 1]
                                 + red[tid * 4 + 2] + red[tid * 4 + 3] + b3[0];
                }
            }

            // incremental update for next width
            if (n + 1 < nend) {
#pragma unroll
                for (int it = 0; it < 5; it++) {
                    int idx = tid + it * 512;
                    int i = idx / 40, g = idx - i * 40, c0 = g * 4;
                    float e = eg[i + n];
                    float4 p = *(const float4*)(PP + (size_t)(s0 + i + n) * LDO + c0);
                    float4 ns = *(const float4*)(NS + i * 160 + c0);
                    ns.x += e * p.x; ns.y += e * p.y;
                    ns.z += e * p.z; ns.w += e * p.w;
                    *(float4*)(NS + i * 160 + c0) = ns;
                }
                if (tid < 64) {
                    sD[tid] += eg[tid + n];
                    invD[tid] = 1.f / sD[tid];
                }
            }
            __syncthreads();
        }
    }
}

// ---------------- host ----------------
extern "C" void kernel_launch(void* const* d_in, const int* in_sizes, int n_in,
                              void* d_out, int out_size)
{
    const float* embeds  = (const float*)d_in[0];
    const float* states  = (const float*)d_in[1];
    const float* attn_W1 = (const float*)d_in[2];
    const float* attn_b1 = (const float*)d_in[3];
    const float* attn_W2 = (const float*)d_in[4];
    const float* attn_b2 = (const float*)d_in[5];
    const float* attn_W3 = (const float*)d_in[6];
    const float* attn_b3 = (const float*)d_in[7];
    const float* sc_W1   = (const float*)d_in[8];
    const float* sc_b1   = (const float*)d_in[9];
    const float* sc_W2   = (const float*)d_in[10];
    const float* sc_b2   = (const float*)d_in[11];
    const float* sc_W3   = (const float*)d_in[12];
    const float* sc_b3   = (const float*)d_in[13];
    float* out = (float*)d_out;

    float *AH1, *AP, *BP, *PP, *LG;
    cudaGetSymbolAddress((void**)&AH1, g_AH1);
    cudaGetSymbolAddress((void**)&AP,  g_AP);
    cudaGetSymbolAddress((void**)&BP,  g_BP);
    cudaGetSymbolAddress((void**)&PP,  g_PP);
    cudaGetSymbolAddress((void**)&LG,  g_LG);

    const int gm128 = (T_TOK + 127) / 128;  // 157

    prep_all<<<148, 256>>>(attn_W1, sc_W1, attn_W2, sc_W2,
                           attn_b1, attn_b2, sc_b1, sc_b2, sc_W3, attn_W3);

    gemmA<<<dim3(gm128, 4), 512>>>(states, embeds, AH1, AP, BP, PP);

    attn2_k<<<gm128, 512>>>(AH1, attn_b3, LG);

    cudaFuncSetAttribute(span_k, cudaFuncAttributeMaxDynamicSharedMemorySize, SPAN_SMEM);
    span_k<<<148, 512, SPAN_SMEM>>>(AP, BP, PP, LG, sc_b3, out);
}